// round 6
// baseline (speedup 1.0000x reference)
#include <cuda_runtime.h>
#include <cuda_bf16.h>
#include <mma.h>
#include <math.h>

using namespace nvcuda;

// ---------------- problem constants ----------------
#define BB 4
#define NN 2048
#define MV 576
#define CC 512
#define HH 8
#define KVH 2
#define DD 64
#define EE 8
#define TOPK 2
#define FF 2048
#define TOK (BB*NN)          // 8192 text tokens
#define KVDIM (KVH*DD)       // 128
#define EROWS 8192           // max assignments per expert

// wmma tile paddings
#define APAD 24              // A smem leading dim (bf16), multiple of 8
#define BPAD 136             // B smem leading dim (bf16), multiple of 8
#define CPAD 132             // C staging leading dim (fp32), multiple of 4

// ---------------- static scratch ----------------
__device__ float g_h  [(size_t)TOK*CC];
__device__ float g_q  [(size_t)TOK*CC];
__device__ float g_k  [(size_t)TOK*KVDIM];
__device__ float g_v  [(size_t)TOK*KVDIM];
__device__ float g_att[(size_t)TOK*CC];
__device__ float g_x1 [(size_t)TOK*CC];
__device__ float g_x2 [(size_t)TOK*CC];
__device__ float g_mid[(size_t)EE*EROWS*FF];
__device__ float g_eo [(size_t)EE*EROWS*CC];
__device__ int   g_count[EE];
__device__ float g_Psum[EE];
__device__ int   g_tokrow [TOK*TOPK];
__device__ float g_tokgate[TOK*TOPK];
__device__ int   g_tok_of_row[EE*EROWS];

// ---------------- LayerNorm ----------------
__global__ void ln_kernel(const float* __restrict__ x, const float* __restrict__ g,
                          const float* __restrict__ b, float* __restrict__ o) {
    int t = blockIdx.x;
    int tid = threadIdx.x;                 // 256 threads, C=512
    const float* xr = x + (size_t)t * CC;
    float v0 = xr[tid], v1 = xr[tid + 256];
    __shared__ float red[256];
    red[tid] = v0 + v1; __syncthreads();
    for (int off = 128; off > 0; off >>= 1) {
        if (tid < off) red[tid] += red[tid + off];
        __syncthreads();
    }
    float mu = red[0] * (1.0f / CC);
    __syncthreads();
    float d0 = v0 - mu, d1 = v1 - mu;
    red[tid] = d0 * d0 + d1 * d1; __syncthreads();
    for (int off = 128; off > 0; off >>= 1) {
        if (tid < off) red[tid] += red[tid + off];
        __syncthreads();
    }
    float rstd = rsqrtf(red[0] * (1.0f / CC) + 1e-6f);
    float* orow = o + (size_t)t * CC;
    orow[tid]       = d0 * rstd * g[tid]       + b[tid];
    orow[tid + 256] = d1 * rstd * g[tid + 256] + b[tid + 256];
}

// ---------------- wmma split-bf16 GEMM core (128x128 tile, 256 threads) ----------------
struct SmemGemm {
    __nv_bfloat16 Ah[128][APAD];
    __nv_bfloat16 Al[128][APAD];
    __nv_bfloat16 Bh[16][BPAD];
    __nv_bfloat16 Bl[16][BPAD];
};
#define GEMM_SMEM_BYTES (128*CPAD*4)   // 67,584 (Cs staging; > sizeof(SmemGemm))

typedef wmma::fragment<wmma::accumulator, 16, 16, 16, float> AccFrag;

__device__ __forceinline__ void split_bf16_8(const float* vals, __nv_bfloat16* h, __nv_bfloat16* l) {
    #pragma unroll
    for (int i = 0; i < 8; i++) {
        h[i] = __float2bfloat16(vals[i]);
        l[i] = __float2bfloat16(vals[i] - __bfloat162float(h[i]));
    }
}

// A row source: direct (tokidx==nullptr, rows row0+r guarded by Mr) or gathered via tokidx
__device__ __forceinline__ void wmma_core(
        const float* __restrict__ A, const float* __restrict__ W,
        const int* __restrict__ tokidx,
        int Mr, int Nc, int Kd, int row0, int col0,
        SmemGemm* S, AccFrag (&acc)[2][4]) {
    int tid = threadIdx.x;
    int w = tid >> 5;
    int wm = w & 3, wn = w >> 2;
    #pragma unroll 1
    for (int k0 = 0; k0 < Kd; k0 += 16) {
        {   // load A 128x16, convert to hi/lo bf16
            int r = tid >> 1, kc = (tid & 1) * 8;
            const float* ap;
            bool valid;
            if (tokidx) {
                int tok = tokidx[r];
                valid = (tok >= 0);
                ap = A + (size_t)(valid ? tok : 0) * Kd + k0 + kc;
            } else {
                int gr = row0 + r;
                valid = (gr < Mr);
                ap = A + (size_t)(valid ? gr : 0) * Kd + k0 + kc;
            }
            float4 v0, v1;
            if (valid) { v0 = *(const float4*)ap; v1 = *(const float4*)(ap + 4); }
            else { v0 = make_float4(0.f,0.f,0.f,0.f); v1 = v0; }
            float vals[8] = {v0.x,v0.y,v0.z,v0.w,v1.x,v1.y,v1.z,v1.w};
            __align__(16) __nv_bfloat16 h[8], l[8];
            split_bf16_8(vals, h, l);
            *(uint4*)&S->Ah[r][kc] = *(uint4*)h;
            *(uint4*)&S->Al[r][kc] = *(uint4*)l;
        }
        {   // load B 16x128, convert
            int r = tid >> 4, c0 = (tid & 15) * 8;
            const float* wp = W + (size_t)(k0 + r) * Nc + col0 + c0;
            float4 v0 = *(const float4*)wp, v1 = *(const float4*)(wp + 4);
            float vals[8] = {v0.x,v0.y,v0.z,v0.w,v1.x,v1.y,v1.z,v1.w};
            __align__(16) __nv_bfloat16 h[8], l[8];
            split_bf16_8(vals, h, l);
            *(uint4*)&S->Bh[r][c0] = *(uint4*)h;
            *(uint4*)&S->Bl[r][c0] = *(uint4*)l;
        }
        __syncthreads();
        wmma::fragment<wmma::matrix_a, 16,16,16, __nv_bfloat16, wmma::row_major> ah[2], al[2];
        wmma::fragment<wmma::matrix_b, 16,16,16, __nv_bfloat16, wmma::row_major> bh[4], bl[4];
        #pragma unroll
        for (int i = 0; i < 2; i++) {
            wmma::load_matrix_sync(ah[i], &S->Ah[wm*32 + i*16][0], APAD);
            wmma::load_matrix_sync(al[i], &S->Al[wm*32 + i*16][0], APAD);
        }
        #pragma unroll
        for (int j = 0; j < 4; j++) {
            wmma::load_matrix_sync(bh[j], &S->Bh[0][wn*64 + j*16], BPAD);
            wmma::load_matrix_sync(bl[j], &S->Bl[0][wn*64 + j*16], BPAD);
        }
        #pragma unroll
        for (int i = 0; i < 2; i++)
            #pragma unroll
            for (int j = 0; j < 4; j++) {
                wmma::mma_sync(acc[i][j], ah[i], bh[j], acc[i][j]);
                wmma::mma_sync(acc[i][j], ah[i], bl[j], acc[i][j]);
                wmma::mma_sync(acc[i][j], al[i], bh[j], acc[i][j]);
            }
        __syncthreads();
    }
}

__device__ __forceinline__ void stage_acc(AccFrag (&acc)[2][4], float (*Cs)[CPAD], int tid) {
    int w = tid >> 5;
    int wm = w & 3, wn = w >> 2;
    #pragma unroll
    for (int i = 0; i < 2; i++)
        #pragma unroll
        for (int j = 0; j < 4; j++)
            wmma::store_matrix_sync(&Cs[wm*32 + i*16][wn*64 + j*16], acc[i][j],
                                    CPAD, wmma::mem_row_major);
    __syncthreads();
}

// ---------------- generic GEMM kernel (bias + optional residual) ----------------
__global__ void __launch_bounds__(256) gemm128(
        const float* __restrict__ A, const float* __restrict__ W,
        const float* __restrict__ bias, const float* __restrict__ resid,
        float* __restrict__ out, int Mr, int Nc, int Kd) {
    extern __shared__ char smraw[];
    SmemGemm* S = (SmemGemm*)smraw;
    float (*Cs)[CPAD] = (float(*)[CPAD])smraw;
    int tid = threadIdx.x;
    int row0 = blockIdx.y * 128, col0 = blockIdx.x * 128;
    AccFrag acc[2][4];
    #pragma unroll
    for (int i = 0; i < 2; i++)
        #pragma unroll
        for (int j = 0; j < 4; j++) wmma::fill_fragment(acc[i][j], 0.0f);
    wmma_core(A, W, nullptr, Mr, Nc, Kd, row0, col0, S, acc);
    stage_acc(acc, Cs, tid);
    #pragma unroll
    for (int u = 0; u < 16; u++) {
        int f = tid + u * 256;
        int r = f >> 5, c = (f & 31) * 4;
        int gr = row0 + r;
        if (gr >= Mr) continue;
        int gc = col0 + c;
        float4 v = *(float4*)&Cs[r][c];
        if (bias) {
            v.x += bias[gc]; v.y += bias[gc+1]; v.z += bias[gc+2]; v.w += bias[gc+3];
        }
        if (resid) {
            float4 rr = *(const float4*)(resid + (size_t)gr * Nc + gc);
            v.x += rr.x; v.y += rr.y; v.z += rr.z; v.w += rr.w;
        }
        *(float4*)(out + (size_t)gr * Nc + gc) = v;
    }
}

// ---------------- fused K+V projection (Nc = 128, blockIdx.x selects K or V) ----------------
__global__ void __launch_bounds__(256) kvgemm128(
        const float* __restrict__ A,
        const float* __restrict__ Wk, const float* __restrict__ bk,
        const float* __restrict__ Wv, const float* __restrict__ bv,
        float* __restrict__ outk, float* __restrict__ outv, int Mr, int Kd) {
    extern __shared__ char smraw[];
    SmemGemm* S = (SmemGemm*)smraw;
    float (*Cs)[CPAD] = (float(*)[CPAD])smraw;
    const float* W    = (blockIdx.x == 0) ? Wk : Wv;
    const float* bias = (blockIdx.x == 0) ? bk : bv;
    float* out        = (blockIdx.x == 0) ? outk : outv;
    int tid = threadIdx.x;
    int row0 = blockIdx.y * 128;
    AccFrag acc[2][4];
    #pragma unroll
    for (int i = 0; i < 2; i++)
        #pragma unroll
        for (int j = 0; j < 4; j++) wmma::fill_fragment(acc[i][j], 0.0f);
    wmma_core(A, W, nullptr, Mr, KVDIM, Kd, row0, 0, S, acc);
    stage_acc(acc, Cs, tid);
    #pragma unroll
    for (int u = 0; u < 16; u++) {
        int f = tid + u * 256;
        int r = f >> 5, c = (f & 31) * 4;
        int gr = row0 + r;
        if (gr >= Mr) continue;
        float4 v = *(float4*)&Cs[r][c];
        v.x += bias[c]; v.y += bias[c+1]; v.z += bias[c+2]; v.w += bias[c+3];
        *(float4*)(out + (size_t)gr * KVDIM + c) = v;
    }
}

// ---------------- flash attention (fp32, unchanged from R5) ----------------
#define FLASH_SMEM_FLOATS (2*64*132 + 64*68)
__global__ void __launch_bounds__(256) flash_kernel(
        const float* __restrict__ Q, const float* __restrict__ K,
        const float* __restrict__ V, float* __restrict__ out,
        int n_kv, int causal) {
    extern __shared__ float sm[];
    float (*Qs)[132] = (float(*)[132])sm;
    float (*KP)[132] = (float(*)[132])(sm + 64 * 132);
    float (*Vs)[68]  = (float(*)[68])(sm + 2 * 64 * 132);
    int qt = blockIdx.x, h = blockIdx.y, b = blockIdx.z;
    int g = h >> 2;
    int tid = threadIdx.x;
    int tx = tid & 15, ty = tid >> 4;

    {
        int qrow = tid >> 1;
        int dh = (tid & 1) * 32;
        const float* qp = Q + ((size_t)(b * NN + qt * 128 + qrow)) * CC + h * DD + dh;
        #pragma unroll
        for (int i = 0; i < 8; i++) {
            float4 v = *(const float4*)(qp + i * 4);
            Qs[dh + i * 4 + 0][qrow] = v.x;
            Qs[dh + i * 4 + 1][qrow] = v.y;
            Qs[dh + i * 4 + 2][qrow] = v.z;
            Qs[dh + i * 4 + 3][qrow] = v.w;
        }
    }

    float m_i[8], l_i[8], o[8][4];
    #pragma unroll
    for (int i = 0; i < 8; i++) {
        m_i[i] = -1e30f; l_i[i] = 0.0f;
        #pragma unroll
        for (int j = 0; j < 4; j++) o[i][j] = 0.0f;
    }

    int lrow = tid >> 2;
    int dseg = (tid & 3) * 16;
    int nkt = causal ? (2 * qt + 2) : (n_kv / 64);
    for (int kt = 0; kt < nkt; kt++) {
        __syncthreads();
        {
            const float* kp = K + ((size_t)(b * n_kv + kt * 64 + lrow)) * KVDIM + g * DD + dseg;
            const float* vp = V + ((size_t)(b * n_kv + kt * 64 + lrow)) * KVDIM + g * DD + dseg;
            #pragma unroll
            for (int q4 = 0; q4 < 4; q4++) {
                float4 kv = *(const float4*)(kp + q4 * 4);
                KP[dseg + q4 * 4 + 0][lrow] = kv.x;
                KP[dseg + q4 * 4 + 1][lrow] = kv.y;
                KP[dseg + q4 * 4 + 2][lrow] = kv.z;
                KP[dseg + q4 * 4 + 3][lrow] = kv.w;
                *(float4*)(&Vs[lrow][dseg + q4 * 4]) = *(const float4*)(vp + q4 * 4);
            }
        }
        __syncthreads();

        float s[8][4] = {};
        #pragma unroll
        for (int d = 0; d < 64; d++) {
            float4 a0 = *(const float4*)(&Qs[d][ty * 4]);
            float4 a1 = *(const float4*)(&Qs[d][ty * 4 + 64]);
            float4 bb = *(const float4*)(&KP[d][tx * 4]);
            float av[8] = {a0.x, a0.y, a0.z, a0.w, a1.x, a1.y, a1.z, a1.w};
            float bv[4] = {bb.x, bb.y, bb.z, bb.w};
            #pragma unroll
            for (int i = 0; i < 8; i++)
                #pragma unroll
                for (int j = 0; j < 4; j++)
                    s[i][j] += av[i] * bv[j];
        }
        bool maskit = causal && (kt >= 2 * qt);
        #pragma unroll
        for (int i = 0; i < 8; i++) {
            int rg = qt * 128 + ((i < 4) ? (ty * 4 + i) : (64 + ty * 4 + i - 4));
            #pragma unroll
            for (int j = 0; j < 4; j++) {
                float v = s[i][j] * 0.125f;
                if (maskit && (kt * 64 + tx * 4 + j) > rg) v = -1e9f;
                s[i][j] = v;
            }
        }
        #pragma unroll
        for (int i = 0; i < 8; i++) {
            float rm = fmaxf(fmaxf(s[i][0], s[i][1]), fmaxf(s[i][2], s[i][3]));
            #pragma unroll
            for (int off = 8; off; off >>= 1)
                rm = fmaxf(rm, __shfl_xor_sync(0xffffffffu, rm, off));
            float mn = fmaxf(m_i[i], rm);
            float alpha = __expf(m_i[i] - mn);
            m_i[i] = mn;
            float rs = 0.0f;
            #pragma unroll
            for (int j = 0; j < 4; j++) {
                s[i][j] = __expf(s[i][j] - mn);
                rs += s[i][j];
            }
            #pragma unroll
            for (int off = 8; off; off >>= 1)
                rs += __shfl_xor_sync(0xffffffffu, rs, off);
            l_i[i] = l_i[i] * alpha + rs;
            #pragma unroll
            for (int j = 0; j < 4; j++) o[i][j] *= alpha;
        }
        __syncthreads();
        #pragma unroll
        for (int i = 0; i < 8; i++) {
            int qr = (i < 4) ? (ty * 4 + i) : (64 + ty * 4 + i - 4);
            #pragma unroll
            for (int j = 0; j < 4; j++)
                KP[tx * 4 + j][qr] = s[i][j];
        }
        __syncthreads();
        #pragma unroll
        for (int k = 0; k < 64; k++) {
            float4 p0 = *(const float4*)(&KP[k][ty * 4]);
            float4 p1 = *(const float4*)(&KP[k][ty * 4 + 64]);
            float4 vv = *(const float4*)(&Vs[k][tx * 4]);
            float pv[8] = {p0.x, p0.y, p0.z, p0.w, p1.x, p1.y, p1.z, p1.w};
            float va[4] = {vv.x, vv.y, vv.z, vv.w};
            #pragma unroll
            for (int i = 0; i < 8; i++)
                #pragma unroll
                for (int j = 0; j < 4; j++)
                    o[i][j] += pv[i] * va[j];
        }
    }
    #pragma unroll
    for (int i = 0; i < 8; i++) {
        float inv = 1.0f / l_i[i];
        int row = qt * 128 + ((i < 4) ? (ty * 4 + i) : (64 + ty * 4 + i - 4));
        float4 w = make_float4(o[i][0] * inv, o[i][1] * inv, o[i][2] * inv, o[i][3] * inv);
        *(float4*)(&out[((size_t)(b * NN + row)) * CC + h * DD + tx * 4]) = w;
    }
}

// ---------------- MoE routing ----------------
__global__ void zero_kernel() {
    int t = threadIdx.x;
    if (t < EE) { g_count[t] = 0; g_Psum[t] = 0.0f; }
}

__global__ void router_kernel(const float* __restrict__ rw, const float* __restrict__ rb) {
    __shared__ float sP[EE];
    int tid = threadIdx.x;
    if (tid < EE) sP[tid] = 0.0f;
    __syncthreads();
    int t = blockIdx.x * blockDim.x + tid;
    float logit[EE];
    const float* hrow = g_h + (size_t)t * CC;
    #pragma unroll
    for (int e = 0; e < EE; e++) logit[e] = rb[e];
    for (int k = 0; k < CC; k++) {
        float hv = hrow[k];
        const float* wr = rw + k * EE;
        #pragma unroll
        for (int e = 0; e < EE; e++) logit[e] += hv * wr[e];
    }
    float mx = logit[0];
    #pragma unroll
    for (int e = 1; e < EE; e++) mx = fmaxf(mx, logit[e]);
    float p[EE], ps = 0.0f;
    #pragma unroll
    for (int e = 0; e < EE; e++) { p[e] = __expf(logit[e] - mx); ps += p[e]; }
    float invs = 1.0f / ps;
    #pragma unroll
    for (int e = 0; e < EE; e++) p[e] *= invs;
    int i0 = 0;
    #pragma unroll
    for (int e = 1; e < EE; e++) if (p[e] > p[i0]) i0 = e;
    int i1 = (i0 == 0) ? 1 : 0;
    #pragma unroll
    for (int e = 0; e < EE; e++) if (e != i0 && p[e] > p[i1]) i1 = e;
    float gs = p[i0] + p[i1];
    float g0 = p[i0] / gs, g1 = p[i1] / gs;
    int s0 = atomicAdd(&g_count[i0], 1);
    int s1 = atomicAdd(&g_count[i1], 1);
    int r0 = i0 * EROWS + s0, r1 = i1 * EROWS + s1;
    g_tok_of_row[r0] = t; g_tok_of_row[r1] = t;
    g_tokrow[t * 2] = r0; g_tokrow[t * 2 + 1] = r1;
    g_tokgate[t * 2] = g0; g_tokgate[t * 2 + 1] = g1;
    #pragma unroll
    for (int e = 0; e < EE; e++) atomicAdd(&sP[e], p[e]);
    __syncthreads();
    if (tid < EE) atomicAdd(&g_Psum[tid], sP[tid]);
}

// ---------------- expert GEMM 1 (gathered A, GELU) ----------------
__global__ void __launch_bounds__(256) egemm1_kernel(const float* __restrict__ ew1,
                                                     const float* __restrict__ eb1) {
    int e = blockIdx.z;
    int cnt = g_count[e];
    int row0 = blockIdx.y * 128;
    if (row0 >= cnt) return;
    int col0 = blockIdx.x * 128;
    extern __shared__ char smraw[];
    SmemGemm* S = (SmemGemm*)smraw;
    float (*Cs)[CPAD] = (float(*)[CPAD])smraw;
    __shared__ int s_tok[128];
    int tid = threadIdx.x;
    if (tid < 128) {
        int gr = row0 + tid;
        s_tok[tid] = (gr < cnt) ? g_tok_of_row[e * EROWS + gr] : -1;
    }
    __syncthreads();
    AccFrag acc[2][4];
    #pragma unroll
    for (int i = 0; i < 2; i++)
        #pragma unroll
        for (int j = 0; j < 4; j++) wmma::fill_fragment(acc[i][j], 0.0f);
    wmma_core(g_h, ew1 + (size_t)e * CC * FF, s_tok, 0, FF, CC, 0, col0, S, acc);
    stage_acc(acc, Cs, tid);
    #pragma unroll
    for (int u = 0; u < 16; u++) {
        int f = tid + u * 256;
        int r = f >> 5, c = (f & 31) * 4;
        if (row0 + r >= cnt) continue;
        int gc = col0 + c;
        float4 v = *(float4*)&Cs[r][c];
        float* dst = &g_mid[((size_t)e * EROWS + row0 + r) * FF + gc];
        float vv[4] = {v.x, v.y, v.z, v.w};
        float4 res;
        float* rp = &res.x;
        #pragma unroll
        for (int j = 0; j < 4; j++) {
            float xx = vv[j] + eb1[e * FF + gc + j];
            float uu = 0.7978845608028654f * (xx + 0.044715f * xx * xx * xx);
            rp[j] = 0.5f * xx * (1.0f + tanhf(uu));
        }
        *(float4*)dst = res;
    }
}

// ---------------- expert GEMM 2 ----------------
__global__ void __launch_bounds__(256) egemm2_kernel(const float* __restrict__ ew2,
                                                     const float* __restrict__ eb2) {
    int e = blockIdx.z;
    int cnt = g_count[e];
    int row0 = blockIdx.y * 128;
    if (row0 >= cnt) return;
    int col0 = blockIdx.x * 128;
    extern __shared__ char smraw[];
    SmemGemm* S = (SmemGemm*)smraw;
    float (*Cs)[CPAD] = (float(*)[CPAD])smraw;
    int tid = threadIdx.x;
    AccFrag acc[2][4];
    #pragma unroll
    for (int i = 0; i < 2; i++)
        #pragma unroll
        for (int j = 0; j < 4; j++) wmma::fill_fragment(acc[i][j], 0.0f);
    wmma_core(g_mid + (size_t)e * EROWS * FF, ew2 + (size_t)e * FF * CC,
              nullptr, cnt, CC, FF, row0, col0, S, acc);
    stage_acc(acc, Cs, tid);
    #pragma unroll
    for (int u = 0; u < 16; u++) {
        int f = tid + u * 256;
        int r = f >> 5, c = (f & 31) * 4;
        if (row0 + r >= cnt) continue;
        int gc = col0 + c;
        float4 v = *(float4*)&Cs[r][c];
        v.x += eb2[e * CC + gc];     v.y += eb2[e * CC + gc + 1];
        v.z += eb2[e * CC + gc + 2]; v.w += eb2[e * CC + gc + 3];
        *(float4*)&g_eo[((size_t)e * EROWS + row0 + r) * CC + gc] = v;
    }
}

// ---------------- combine + aux ----------------
__global__ void combine_kernel(float* __restrict__ out) {
    int t = blockIdx.x;
    int tid = threadIdx.x;
    int r0 = g_tokrow[t * 2], r1 = g_tokrow[t * 2 + 1];
    float g0 = g_tokgate[t * 2], g1 = g_tokgate[t * 2 + 1];
    const float* x2 = g_x2 + (size_t)t * CC;
    const float* e0 = g_eo + (size_t)r0 * CC;
    const float* e1 = g_eo + (size_t)r1 * CC;
    float* orow = out + (size_t)t * CC;
    for (int c = tid; c < CC; c += 128)
        orow[c] = x2[c] + g0 * e0[c] + g1 * e1[c];
}

__global__ void aux_kernel(float* __restrict__ out, int out_size) {
    if (threadIdx.x == 0 && blockIdx.x == 0) {
        float a = 0.0f;
        for (int e = 0; e < EE; e++)
            a += (g_count[e] / (float)TOK) * (g_Psum[e] / (float)TOK);
        a *= (float)EE;
        if (out_size > TOK * CC) out[TOK * CC] = a;
    }
}

// ---------------- launch ----------------
extern "C" void kernel_launch(void* const* d_in, const int* in_sizes, int n_in,
                              void* d_out, int out_size) {
    const float* x      = (const float*)d_in[0];
    const float* vision = (const float*)d_in[1];
    const float* ln1_g = (const float*)d_in[2];  const float* ln1_b = (const float*)d_in[3];
    const float* ln2_g = (const float*)d_in[4];  const float* ln2_b = (const float*)d_in[5];
    const float* ln3_g = (const float*)d_in[6];  const float* ln3_b = (const float*)d_in[7];
    const float* sa_wq = (const float*)d_in[8];  const float* sa_bq = (const float*)d_in[9];
    const float* sa_wk = (const float*)d_in[10]; const float* sa_bk = (const float*)d_in[11];
    const float* sa_wv = (const float*)d_in[12]; const float* sa_bv = (const float*)d_in[13];
    const float* sa_wo = (const float*)d_in[14]; const float* sa_bo = (const float*)d_in[15];
    const float* ca_wq = (const float*)d_in[16]; const float* ca_bq = (const float*)d_in[17];
    const float* ca_wk = (const float*)d_in[18]; const float* ca_bk = (const float*)d_in[19];
    const float* ca_wv = (const float*)d_in[20]; const float* ca_bv = (const float*)d_in[21];
    const float* ca_wo = (const float*)d_in[22]; const float* ca_bo = (const float*)d_in[23];
    const float* rw    = (const float*)d_in[24]; const float* rb    = (const float*)d_in[25];
    const float* ew1   = (const float*)d_in[26]; const float* eb1   = (const float*)d_in[27];
    const float* ew2   = (const float*)d_in[28]; const float* eb2   = (const float*)d_in[29];
    float* out = (float*)d_out;

    float *p_h, *p_q, *p_k, *p_v, *p_att, *p_x1, *p_x2;
    cudaGetSymbolAddress((void**)&p_h,  g_h);
    cudaGetSymbolAddress((void**)&p_q,  g_q);
    cudaGetSymbolAddress((void**)&p_k,  g_k);
    cudaGetSymbolAddress((void**)&p_v,  g_v);
    cudaGetSymbolAddress((void**)&p_att, g_att);
    cudaGetSymbolAddress((void**)&p_x1, g_x1);
    cudaGetSymbolAddress((void**)&p_x2, g_x2);

    const int flash_smem = FLASH_SMEM_FLOATS * (int)sizeof(float);   // 84,992 B
    const int gemm_smem  = GEMM_SMEM_BYTES;                          // 67,584 B
    cudaFuncSetAttribute(flash_kernel,  cudaFuncAttributeMaxDynamicSharedMemorySize, flash_smem);
    cudaFuncSetAttribute(gemm128,       cudaFuncAttributeMaxDynamicSharedMemorySize, gemm_smem);
    cudaFuncSetAttribute(kvgemm128,     cudaFuncAttributeMaxDynamicSharedMemorySize, gemm_smem);
    cudaFuncSetAttribute(egemm1_kernel, cudaFuncAttributeMaxDynamicSharedMemorySize, gemm_smem);
    cudaFuncSetAttribute(egemm2_kernel, cudaFuncAttributeMaxDynamicSharedMemorySize, gemm_smem);

    dim3 gC(CC / 128, TOK / 128);            // 4 x 64
    dim3 gKVsa(2, TOK / 128);
    dim3 gKVca(2, (BB * MV) / 128);          // 2304 = 18*128
    dim3 gAtt(NN / 128, HH, BB);

    // --- block 1: pre-norm causal GQA self-attn + residual ---
    ln_kernel<<<TOK, 256>>>(x, ln1_g, ln1_b, p_h);
    gemm128<<<gC, 256, gemm_smem>>>(p_h, sa_wq, sa_bq, nullptr, p_q, TOK, CC, CC);
    kvgemm128<<<gKVsa, 256, gemm_smem>>>(p_h, sa_wk, sa_bk, sa_wv, sa_bv, p_k, p_v, TOK, CC);
    flash_kernel<<<gAtt, 256, flash_smem>>>(p_q, p_k, p_v, p_att, NN, 1);
    gemm128<<<gC, 256, gemm_smem>>>(p_att, sa_wo, sa_bo, x, p_x1, TOK, CC, CC);

    // --- block 2: pre-norm cross-attn + residual ---
    ln_kernel<<<TOK, 256>>>(p_x1, ln2_g, ln2_b, p_h);
    gemm128<<<gC, 256, gemm_smem>>>(p_h, ca_wq, ca_bq, nullptr, p_q, TOK, CC, CC);
    kvgemm128<<<gKVca, 256, gemm_smem>>>(vision, ca_wk, ca_bk, ca_wv, ca_bv, p_k, p_v, BB * MV, CC);
    flash_kernel<<<gAtt, 256, flash_smem>>>(p_q, p_k, p_v, p_att, MV, 0);
    gemm128<<<gC, 256, gemm_smem>>>(p_att, ca_wo, ca_bo, p_x1, p_x2, TOK, CC, CC);

    // --- block 3: pre-norm MoE + residual (sparse: only routed experts) ---
    ln_kernel<<<TOK, 256>>>(p_x2, ln3_g, ln3_b, p_h);
    zero_kernel<<<1, 32>>>();
    router_kernel<<<TOK / 256, 256>>>(rw, rb);
    egemm1_kernel<<<dim3(FF / 128, EROWS / 128, EE), 256, gemm_smem>>>(ew1, eb1);
    egemm2_kernel<<<dim3(CC / 128, EROWS / 128, EE), 256, gemm_smem>>>(ew2, eb2);
    combine_kernel<<<TOK, 128>>>(out);
    aux_kernel<<<1, 1>>>(out, out_size);
}

// round 7
// speedup vs baseline: 1.3595x; 1.3595x over previous
#include <cuda_runtime.h>
#include <cuda_bf16.h>
#include <mma.h>
#include <math.h>

using namespace nvcuda;

// ---------------- problem constants ----------------
#define BB 4
#define NN 2048
#define MV 576
#define CC 512
#define HH 8
#define KVH 2
#define DD 64
#define EE 8
#define TOPK 2
#define FF 2048
#define TOK (BB*NN)
#define KVDIM (KVH*DD)       // 128
#define EROWS 8192

// weight buffer offsets (elements)
#define SZ_QO (CC*CC)
#define SZ_KV (CC*KVDIM)
#define OFF_SAWQ 0
#define OFF_SAWK (OFF_SAWQ+SZ_QO)
#define OFF_SAWV (OFF_SAWK+SZ_KV)
#define OFF_SAWO (OFF_SAWV+SZ_KV)
#define OFF_CAWQ (OFF_SAWO+SZ_QO)
#define OFF_CAWK (OFF_CAWQ+SZ_QO)
#define OFF_CAWV (OFF_CAWK+SZ_KV)
#define OFF_CAWO (OFF_CAWV+SZ_KV)
#define OFF_EW1  (OFF_CAWO+SZ_QO)
#define OFF_EW2  (OFF_EW1 + (size_t)EE*CC*FF)
#define WTOT     (OFF_EW2 + (size_t)EE*FF*CC)

// ---------------- static scratch ----------------
__device__ float g_h  [(size_t)TOK*CC];     // fp32 LN out (router)
__device__ float g_q  [(size_t)TOK*CC];
__device__ float g_k  [(size_t)TOK*KVDIM];
__device__ float g_v  [(size_t)TOK*KVDIM];
__device__ float g_x1 [(size_t)TOK*CC];
__device__ float g_x2 [(size_t)TOK*CC];
__device__ float g_eo [(size_t)EE*EROWS*CC];
__device__ __nv_bfloat16 g_h_hi [(size_t)TOK*CC];
__device__ __nv_bfloat16 g_h_lo [(size_t)TOK*CC];
__device__ __nv_bfloat16 g_att_hi[(size_t)TOK*CC];
__device__ __nv_bfloat16 g_att_lo[(size_t)TOK*CC];
__device__ __nv_bfloat16 g_vis_hi[(size_t)BB*MV*CC];
__device__ __nv_bfloat16 g_vis_lo[(size_t)BB*MV*CC];
__device__ __nv_bfloat16 g_mid_hi[(size_t)EE*EROWS*FF];
__device__ __nv_bfloat16 g_mid_lo[(size_t)EE*EROWS*FF];
__device__ __nv_bfloat16 g_w_hi[WTOT];
__device__ __nv_bfloat16 g_w_lo[WTOT];
__device__ int   g_count[EE];
__device__ float g_Psum[EE];
__device__ int   g_tokrow [TOK*TOPK];
__device__ float g_tokgate[TOK*TOPK];
__device__ int   g_tok_of_row[EE*EROWS];

// ---------------- split helpers ----------------
__device__ __forceinline__ void split1(float v, __nv_bfloat16& h, __nv_bfloat16& l) {
    h = __float2bfloat16(v);
    l = __float2bfloat16(v - __bfloat162float(h));
}

// ---------------- fp32 -> hi/lo bf16 conversion (vectorized) ----------------
__global__ void conv_kernel(const float* __restrict__ src, __nv_bfloat16* __restrict__ hi,
                            __nv_bfloat16* __restrict__ lo, int n) {
    int i = (blockIdx.x * blockDim.x + threadIdx.x) * 4;
    if (i >= n) return;
    float4 v = *(const float4*)(src + i);
    __align__(8) __nv_bfloat16 h[4], l[4];
    split1(v.x, h[0], l[0]); split1(v.y, h[1], l[1]);
    split1(v.z, h[2], l[2]); split1(v.w, h[3], l[3]);
    *(uint2*)(hi + i) = *(uint2*)h;
    *(uint2*)(lo + i) = *(uint2*)l;
}

// ---------------- LayerNorm (writes fp32 + hi/lo bf16) ----------------
__global__ void ln_kernel(const float* __restrict__ x, const float* __restrict__ g,
                          const float* __restrict__ b, float* __restrict__ o,
                          __nv_bfloat16* __restrict__ ohi, __nv_bfloat16* __restrict__ olo) {
    int t = blockIdx.x;
    int tid = threadIdx.x;
    const float* xr = x + (size_t)t * CC;
    float v0 = xr[tid], v1 = xr[tid + 256];
    __shared__ float red[256];
    red[tid] = v0 + v1; __syncthreads();
    for (int off = 128; off > 0; off >>= 1) {
        if (tid < off) red[tid] += red[tid + off];
        __syncthreads();
    }
    float mu = red[0] * (1.0f / CC);
    __syncthreads();
    float d0 = v0 - mu, d1 = v1 - mu;
    red[tid] = d0 * d0 + d1 * d1; __syncthreads();
    for (int off = 128; off > 0; off >>= 1) {
        if (tid < off) red[tid] += red[tid + off];
        __syncthreads();
    }
    float rstd = rsqrtf(red[0] * (1.0f / CC) + 1e-6f);
    size_t base = (size_t)t * CC;
    float r0 = d0 * rstd * g[tid]       + b[tid];
    float r1 = d1 * rstd * g[tid + 256] + b[tid + 256];
    o[base + tid] = r0; o[base + tid + 256] = r1;
    __nv_bfloat16 h, l;
    split1(r0, h, l); ohi[base + tid] = h;       olo[base + tid] = l;
    split1(r1, h, l); ohi[base + tid + 256] = h; olo[base + tid + 256] = l;
}

// ---------------- wmma split-bf16 GEMM core (128x128 tile, K-chunk 32) ----------------
#define APAD 40
#define BPAD 136
#define CPAD 132
struct SmemGemm {
    __nv_bfloat16 Ah[128][APAD];
    __nv_bfloat16 Al[128][APAD];
    __nv_bfloat16 Bh[32][BPAD];
    __nv_bfloat16 Bl[32][BPAD];
};
#define GEMM_SMEM_BYTES (128*CPAD*4)   // 67,584 (Cs staging aliases everything)

typedef wmma::fragment<wmma::accumulator, 16, 16, 16, float> AccFrag;

__device__ __forceinline__ void wmma_core(
        const __nv_bfloat16* __restrict__ Ahg, const __nv_bfloat16* __restrict__ Alg,
        const __nv_bfloat16* __restrict__ Bhg, const __nv_bfloat16* __restrict__ Blg,
        const int* __restrict__ tokidx,
        int Mr, int Nc, int Kd, int row0, int col0,
        SmemGemm* S, AccFrag (&acc)[2][4]) {
    int tid = threadIdx.x;
    int w = tid >> 5, wm = w & 3, wn = w >> 2;
    const uint4 z4 = make_uint4(0u, 0u, 0u, 0u);
    int ra = tid >> 1, kc = (tid & 1) * 16;          // A: 128 rows x 32
    int rb = tid >> 3, cb = (tid & 7) * 16;          // B: 32 rows x 128
    #pragma unroll 1
    for (int k0 = 0; k0 < Kd; k0 += 32) {
        size_t abase; bool valid;
        if (tokidx) {
            int tok = tokidx[ra];
            valid = (tok >= 0);
            abase = (size_t)(valid ? tok : 0) * Kd + k0 + kc;
        } else {
            int gr = row0 + ra;
            valid = (gr < Mr);
            abase = (size_t)(valid ? gr : 0) * Kd + k0 + kc;
        }
        uint4 a0 = valid ? *(const uint4*)(Ahg + abase) : z4;
        uint4 a1 = valid ? *(const uint4*)(Ahg + abase + 8) : z4;
        uint4 a2 = valid ? *(const uint4*)(Alg + abase) : z4;
        uint4 a3 = valid ? *(const uint4*)(Alg + abase + 8) : z4;
        *(uint4*)&S->Ah[ra][kc]     = a0;
        *(uint4*)&S->Ah[ra][kc + 8] = a1;
        *(uint4*)&S->Al[ra][kc]     = a2;
        *(uint4*)&S->Al[ra][kc + 8] = a3;
        size_t bbase = (size_t)(k0 + rb) * Nc + col0 + cb;
        uint4 b0 = *(const uint4*)(Bhg + bbase);
        uint4 b1 = *(const uint4*)(Bhg + bbase + 8);
        uint4 b2 = *(const uint4*)(Blg + bbase);
        uint4 b3 = *(const uint4*)(Blg + bbase + 8);
        *(uint4*)&S->Bh[rb][cb]     = b0;
        *(uint4*)&S->Bh[rb][cb + 8] = b1;
        *(uint4*)&S->Bl[rb][cb]     = b2;
        *(uint4*)&S->Bl[rb][cb + 8] = b3;
        __syncthreads();
        #pragma unroll
        for (int ks = 0; ks < 2; ks++) {
            wmma::fragment<wmma::matrix_a, 16,16,16, __nv_bfloat16, wmma::row_major> ah[2], al[2];
            wmma::fragment<wmma::matrix_b, 16,16,16, __nv_bfloat16, wmma::row_major> bh[4], bl[4];
            #pragma unroll
            for (int i = 0; i < 2; i++) {
                wmma::load_matrix_sync(ah[i], &S->Ah[wm*32 + i*16][ks*16], APAD);
                wmma::load_matrix_sync(al[i], &S->Al[wm*32 + i*16][ks*16], APAD);
            }
            #pragma unroll
            for (int j = 0; j < 4; j++) {
                wmma::load_matrix_sync(bh[j], &S->Bh[ks*16][wn*64 + j*16], BPAD);
                wmma::load_matrix_sync(bl[j], &S->Bl[ks*16][wn*64 + j*16], BPAD);
            }
            #pragma unroll
            for (int i = 0; i < 2; i++)
                #pragma unroll
                for (int j = 0; j < 4; j++) {
                    wmma::mma_sync(acc[i][j], ah[i], bh[j], acc[i][j]);
                    wmma::mma_sync(acc[i][j], ah[i], bl[j], acc[i][j]);
                    wmma::mma_sync(acc[i][j], al[i], bh[j], acc[i][j]);
                }
        }
        __syncthreads();
    }
}

__device__ __forceinline__ void stage_acc(AccFrag (&acc)[2][4], float (*Cs)[CPAD], int tid) {
    int w = tid >> 5, wm = w & 3, wn = w >> 2;
    #pragma unroll
    for (int i = 0; i < 2; i++)
        #pragma unroll
        for (int j = 0; j < 4; j++)
            wmma::store_matrix_sync(&Cs[wm*32 + i*16][wn*64 + j*16], acc[i][j],
                                    CPAD, wmma::mem_row_major);
    __syncthreads();
}

// ---------------- generic GEMM (bias + optional residual, fp32 out) ----------------
__global__ void __launch_bounds__(256) gemm128(
        const __nv_bfloat16* __restrict__ Ahg, const __nv_bfloat16* __restrict__ Alg,
        int woff, const float* __restrict__ bias, const float* __restrict__ resid,
        float* __restrict__ out, int Mr, int Nc, int Kd) {
    extern __shared__ char smraw[];
    SmemGemm* S = (SmemGemm*)smraw;
    float (*Cs)[CPAD] = (float(*)[CPAD])smraw;
    int tid = threadIdx.x;
    int row0 = blockIdx.y * 128, col0 = blockIdx.x * 128;
    AccFrag acc[2][4];
    #pragma unroll
    for (int i = 0; i < 2; i++)
        #pragma unroll
        for (int j = 0; j < 4; j++) wmma::fill_fragment(acc[i][j], 0.0f);
    wmma_core(Ahg, Alg, g_w_hi + woff, g_w_lo + woff, nullptr, Mr, Nc, Kd, row0, col0, S, acc);
    stage_acc(acc, Cs, tid);
    #pragma unroll
    for (int u = 0; u < 16; u++) {
        int f = tid + u * 256;
        int r = f >> 5, c = (f & 31) * 4;
        int gr = row0 + r;
        if (gr >= Mr) continue;
        int gc = col0 + c;
        float4 v = *(float4*)&Cs[r][c];
        if (bias) { v.x += bias[gc]; v.y += bias[gc+1]; v.z += bias[gc+2]; v.w += bias[gc+3]; }
        if (resid) {
            float4 rr = *(const float4*)(resid + (size_t)gr * Nc + gc);
            v.x += rr.x; v.y += rr.y; v.z += rr.z; v.w += rr.w;
        }
        *(float4*)(out + (size_t)gr * Nc + gc) = v;
    }
}

// ---------------- fused K+V projection ----------------
__global__ void __launch_bounds__(256) kvgemm128(
        const __nv_bfloat16* __restrict__ Ahg, const __nv_bfloat16* __restrict__ Alg,
        int woffk, const float* __restrict__ bk,
        int woffv, const float* __restrict__ bv,
        float* __restrict__ outk, float* __restrict__ outv, int Mr, int Kd) {
    extern __shared__ char smraw[];
    SmemGemm* S = (SmemGemm*)smraw;
    float (*Cs)[CPAD] = (float(*)[CPAD])smraw;
    int woff          = (blockIdx.x == 0) ? woffk : woffv;
    const float* bias = (blockIdx.x == 0) ? bk : bv;
    float* out        = (blockIdx.x == 0) ? outk : outv;
    int tid = threadIdx.x;
    int row0 = blockIdx.y * 128;
    AccFrag acc[2][4];
    #pragma unroll
    for (int i = 0; i < 2; i++)
        #pragma unroll
        for (int j = 0; j < 4; j++) wmma::fill_fragment(acc[i][j], 0.0f);
    wmma_core(Ahg, Alg, g_w_hi + woff, g_w_lo + woff, nullptr, Mr, KVDIM, Kd, row0, 0, S, acc);
    stage_acc(acc, Cs, tid);
    #pragma unroll
    for (int u = 0; u < 16; u++) {
        int f = tid + u * 256;
        int r = f >> 5, c = (f & 31) * 4;
        int gr = row0 + r;
        if (gr >= Mr) continue;
        float4 v = *(float4*)&Cs[r][c];
        v.x += bias[c]; v.y += bias[c+1]; v.z += bias[c+2]; v.w += bias[c+3];
        *(float4*)(out + (size_t)gr * KVDIM + c) = v;
    }
}

// ---------------- flash attention (fp32 core; epilogue writes hi/lo bf16) ----------------
#define FLASH_SMEM_FLOATS (2*64*132 + 64*68)
__global__ void __launch_bounds__(256) flash_kernel(
        const float* __restrict__ Q, const float* __restrict__ K,
        const float* __restrict__ V,
        __nv_bfloat16* __restrict__ ohi, __nv_bfloat16* __restrict__ olo,
        int n_kv, int causal) {
    extern __shared__ float sm[];
    float (*Qs)[132] = (float(*)[132])sm;
    float (*KP)[132] = (float(*)[132])(sm + 64 * 132);
    float (*Vs)[68]  = (float(*)[68])(sm + 2 * 64 * 132);
    int qt = blockIdx.x, h = blockIdx.y, b = blockIdx.z;
    int g = h >> 2;
    int tid = threadIdx.x;
    int tx = tid & 15, ty = tid >> 4;

    {
        int qrow = tid >> 1;
        int dh = (tid & 1) * 32;
        const float* qp = Q + ((size_t)(b * NN + qt * 128 + qrow)) * CC + h * DD + dh;
        #pragma unroll
        for (int i = 0; i < 8; i++) {
            float4 v = *(const float4*)(qp + i * 4);
            Qs[dh + i * 4 + 0][qrow] = v.x;
            Qs[dh + i * 4 + 1][qrow] = v.y;
            Qs[dh + i * 4 + 2][qrow] = v.z;
            Qs[dh + i * 4 + 3][qrow] = v.w;
        }
    }

    float m_i[8], l_i[8], o[8][4];
    #pragma unroll
    for (int i = 0; i < 8; i++) {
        m_i[i] = -1e30f; l_i[i] = 0.0f;
        #pragma unroll
        for (int j = 0; j < 4; j++) o[i][j] = 0.0f;
    }

    int lrow = tid >> 2;
    int dseg = (tid & 3) * 16;
    int nkt = causal ? (2 * qt + 2) : (n_kv / 64);
    for (int kt = 0; kt < nkt; kt++) {
        __syncthreads();
        {
            const float* kp = K + ((size_t)(b * n_kv + kt * 64 + lrow)) * KVDIM + g * DD + dseg;
            const float* vp = V + ((size_t)(b * n_kv + kt * 64 + lrow)) * KVDIM + g * DD + dseg;
            #pragma unroll
            for (int q4 = 0; q4 < 4; q4++) {
                float4 kv = *(const float4*)(kp + q4 * 4);
                KP[dseg + q4 * 4 + 0][lrow] = kv.x;
                KP[dseg + q4 * 4 + 1][lrow] = kv.y;
                KP[dseg + q4 * 4 + 2][lrow] = kv.z;
                KP[dseg + q4 * 4 + 3][lrow] = kv.w;
                *(float4*)(&Vs[lrow][dseg + q4 * 4]) = *(const float4*)(vp + q4 * 4);
            }
        }
        __syncthreads();

        float s[8][4] = {};
        #pragma unroll
        for (int d = 0; d < 64; d++) {
            float4 a0 = *(const float4*)(&Qs[d][ty * 4]);
            float4 a1 = *(const float4*)(&Qs[d][ty * 4 + 64]);
            float4 bb = *(const float4*)(&KP[d][tx * 4]);
            float av[8] = {a0.x, a0.y, a0.z, a0.w, a1.x, a1.y, a1.z, a1.w};
            float bv[4] = {bb.x, bb.y, bb.z, bb.w};
            #pragma unroll
            for (int i = 0; i < 8; i++)
                #pragma unroll
                for (int j = 0; j < 4; j++)
                    s[i][j] += av[i] * bv[j];
        }
        bool maskit = causal && (kt >= 2 * qt);
        #pragma unroll
        for (int i = 0; i < 8; i++) {
            int rg = qt * 128 + ((i < 4) ? (ty * 4 + i) : (64 + ty * 4 + i - 4));
            #pragma unroll
            for (int j = 0; j < 4; j++) {
                float v = s[i][j] * 0.125f;
                if (maskit && (kt * 64 + tx * 4 + j) > rg) v = -1e9f;
                s[i][j] = v;
            }
        }
        #pragma unroll
        for (int i = 0; i < 8; i++) {
            float rm = fmaxf(fmaxf(s[i][0], s[i][1]), fmaxf(s[i][2], s[i][3]));
            #pragma unroll
            for (int off = 8; off; off >>= 1)
                rm = fmaxf(rm, __shfl_xor_sync(0xffffffffu, rm, off));
            float mn = fmaxf(m_i[i], rm);
            float alpha = __expf(m_i[i] - mn);
            m_i[i] = mn;
            float rs = 0.0f;
            #pragma unroll
            for (int j = 0; j < 4; j++) {
                s[i][j] = __expf(s[i][j] - mn);
                rs += s[i][j];
            }
            #pragma unroll
            for (int off = 8; off; off >>= 1)
                rs += __shfl_xor_sync(0xffffffffu, rs, off);
            l_i[i] = l_i[i] * alpha + rs;
            #pragma unroll
            for (int j = 0; j < 4; j++) o[i][j] *= alpha;
        }
        __syncthreads();
        #pragma unroll
        for (int i = 0; i < 8; i++) {
            int qr = (i < 4) ? (ty * 4 + i) : (64 + ty * 4 + i - 4);
            #pragma unroll
            for (int j = 0; j < 4; j++)
                KP[tx * 4 + j][qr] = s[i][j];
        }
        __syncthreads();
        #pragma unroll
        for (int k = 0; k < 64; k++) {
            float4 p0 = *(const float4*)(&KP[k][ty * 4]);
            float4 p1 = *(const float4*)(&KP[k][ty * 4 + 64]);
            float4 vv = *(const float4*)(&Vs[k][tx * 4]);
            float pv[8] = {p0.x, p0.y, p0.z, p0.w, p1.x, p1.y, p1.z, p1.w};
            float va[4] = {vv.x, vv.y, vv.z, vv.w};
            #pragma unroll
            for (int i = 0; i < 8; i++)
                #pragma unroll
                for (int j = 0; j < 4; j++)
                    o[i][j] += pv[i] * va[j];
        }
    }
    #pragma unroll
    for (int i = 0; i < 8; i++) {
        float inv = 1.0f / l_i[i];
        int row = qt * 128 + ((i < 4) ? (ty * 4 + i) : (64 + ty * 4 + i - 4));
        size_t idx = ((size_t)(b * NN + row)) * CC + h * DD + tx * 4;
        __align__(8) __nv_bfloat16 hh[4], ll[4];
        #pragma unroll
        for (int j = 0; j < 4; j++) split1(o[i][j] * inv, hh[j], ll[j]);
        *(uint2*)(ohi + idx) = *(uint2*)hh;
        *(uint2*)(olo + idx) = *(uint2*)ll;
    }
}

// ---------------- MoE routing ----------------
__global__ void zero_kernel() {
    int t = threadIdx.x;
    if (t < EE) { g_count[t] = 0; g_Psum[t] = 0.0f; }
}

__global__ void router_kernel(const float* __restrict__ rw, const float* __restrict__ rb) {
    __shared__ float sP[EE];
    int tid = threadIdx.x;
    if (tid < EE) sP[tid] = 0.0f;
    __syncthreads();
    int t = blockIdx.x * blockDim.x + tid;
    float logit[EE];
    const float* hrow = g_h + (size_t)t * CC;
    #pragma unroll
    for (int e = 0; e < EE; e++) logit[e] = rb[e];
    for (int k = 0; k < CC; k++) {
        float hv = hrow[k];
        const float* wr = rw + k * EE;
        #pragma unroll
        for (int e = 0; e < EE; e++) logit[e] += hv * wr[e];
    }
    float mx = logit[0];
    #pragma unroll
    for (int e = 1; e < EE; e++) mx = fmaxf(mx, logit[e]);
    float p[EE], ps = 0.0f;
    #pragma unroll
    for (int e = 0; e < EE; e++) { p[e] = __expf(logit[e] - mx); ps += p[e]; }
    float invs = 1.0f / ps;
    #pragma unroll
    for (int e = 0; e < EE; e++) p[e] *= invs;
    int i0 = 0;
    #pragma unroll
    for (int e = 1; e < EE; e++) if (p[e] > p[i0]) i0 = e;
    int i1 = (i0 == 0) ? 1 : 0;
    #pragma unroll
    for (int e = 0; e < EE; e++) if (e != i0 && p[e] > p[i1]) i1 = e;
    float gs = p[i0] + p[i1];
    float g0 = p[i0] / gs, g1 = p[i1] / gs;
    int s0 = atomicAdd(&g_count[i0], 1);
    int s1 = atomicAdd(&g_count[i1], 1);
    int r0 = i0 * EROWS + s0, r1 = i1 * EROWS + s1;
    g_tok_of_row[r0] = t; g_tok_of_row[r1] = t;
    g_tokrow[t * 2] = r0; g_tokrow[t * 2 + 1] = r1;
    g_tokgate[t * 2] = g0; g_tokgate[t * 2 + 1] = g1;
    #pragma unroll
    for (int e = 0; e < EE; e++) atomicAdd(&sP[e], p[e]);
    __syncthreads();
    if (tid < EE) atomicAdd(&g_Psum[tid], sP[tid]);
}

// ---------------- expert GEMM 1 (gathered A, GELU -> mid hi/lo) ----------------
__global__ void __launch_bounds__(256) egemm1_kernel(const float* __restrict__ eb1) {
    int e = blockIdx.z;
    int cnt = g_count[e];
    int row0 = blockIdx.y * 128;
    if (row0 >= cnt) return;
    int col0 = blockIdx.x * 128;
    extern __shared__ char smraw[];
    SmemGemm* S = (SmemGemm*)smraw;
    float (*Cs)[CPAD] = (float(*)[CPAD])smraw;
    __shared__ int s_tok[128];
    int tid = threadIdx.x;
    if (tid < 128) {
        int gr = row0 + tid;
        s_tok[tid] = (gr < cnt) ? g_tok_of_row[e * EROWS + gr] : -1;
    }
    __syncthreads();
    AccFrag acc[2][4];
    #pragma unroll
    for (int i = 0; i < 2; i++)
        #pragma unroll
        for (int j = 0; j < 4; j++) wmma::fill_fragment(acc[i][j], 0.0f);
    size_t woff = OFF_EW1 + (size_t)e * CC * FF;
    wmma_core(g_h_hi, g_h_lo, g_w_hi + woff, g_w_lo + woff, s_tok, 0, FF, CC, 0, col0, S, acc);
    stage_acc(acc, Cs, tid);
    #pragma unroll
    for (int u = 0; u < 16; u++) {
        int f = tid + u * 256;
        int r = f >> 5, c = (f & 31) * 4;
        if (row0 + r >= cnt) continue;
        int gc = col0 + c;
        float4 v = *(float4*)&Cs[r][c];
        float vv[4] = {v.x, v.y, v.z, v.w};
        __align__(8) __nv_bfloat16 hh[4], ll[4];
        #pragma unroll
        for (int j = 0; j < 4; j++) {
            float xx = vv[j] + eb1[e * FF + gc + j];
            float uu = 0.7978845608028654f * (xx + 0.044715f * xx * xx * xx);
            float ge = 0.5f * xx * (1.0f + tanhf(uu));
            split1(ge, hh[j], ll[j]);
        }
        size_t idx = ((size_t)e * EROWS + row0 + r) * FF + gc;
        *(uint2*)(g_mid_hi + idx) = *(uint2*)hh;
        *(uint2*)(g_mid_lo + idx) = *(uint2*)ll;
    }
}

// ---------------- expert GEMM 2 ----------------
__global__ void __launch_bounds__(256) egemm2_kernel(const float* __restrict__ eb2) {
    int e = blockIdx.z;
    int cnt = g_count[e];
    int row0 = blockIdx.y * 128;
    if (row0 >= cnt) return;
    int col0 = blockIdx.x * 128;
    extern __shared__ char smraw[];
    SmemGemm* S = (SmemGemm*)smraw;
    float (*Cs)[CPAD] = (float(*)[CPAD])smraw;
    int tid = threadIdx.x;
    AccFrag acc[2][4];
    #pragma unroll
    for (int i = 0; i < 2; i++)
        #pragma unroll
        for (int j = 0; j < 4; j++) wmma::fill_fragment(acc[i][j], 0.0f);
    size_t woff = OFF_EW2 + (size_t)e * FF * CC;
    wmma_core(g_mid_hi + (size_t)e * EROWS * FF, g_mid_lo + (size_t)e * EROWS * FF,
              g_w_hi + woff, g_w_lo + woff, nullptr, cnt, CC, FF, row0, col0, S, acc);
    stage_acc(acc, Cs, tid);
    #pragma unroll
    for (int u = 0; u < 16; u++) {
        int f = tid + u * 256;
        int r = f >> 5, c = (f & 31) * 4;
        if (row0 + r >= cnt) continue;
        int gc = col0 + c;
        float4 v = *(float4*)&Cs[r][c];
        v.x += eb2[e * CC + gc];     v.y += eb2[e * CC + gc + 1];
        v.z += eb2[e * CC + gc + 2]; v.w += eb2[e * CC + gc + 3];
        *(float4*)&g_eo[((size_t)e * EROWS + row0 + r) * CC + gc] = v;
    }
}

// ---------------- combine + aux ----------------
__global__ void combine_kernel(float* __restrict__ out) {
    int t = blockIdx.x;
    int tid = threadIdx.x;
    int r0 = g_tokrow[t * 2], r1 = g_tokrow[t * 2 + 1];
    float g0 = g_tokgate[t * 2], g1 = g_tokgate[t * 2 + 1];
    const float* x2 = g_x2 + (size_t)t * CC;
    const float* e0 = g_eo + (size_t)r0 * CC;
    const float* e1 = g_eo + (size_t)r1 * CC;
    float* orow = out + (size_t)t * CC;
    for (int c = tid; c < CC; c += 128)
        orow[c] = x2[c] + g0 * e0[c] + g1 * e1[c];
}

__global__ void aux_kernel(float* __restrict__ out, int out_size) {
    if (threadIdx.x == 0 && blockIdx.x == 0) {
        float a = 0.0f;
        for (int e = 0; e < EE; e++)
            a += (g_count[e] / (float)TOK) * (g_Psum[e] / (float)TOK);
        a *= (float)EE;
        if (out_size > TOK * CC) out[TOK * CC] = a;
    }
}

// ---------------- launch ----------------
extern "C" void kernel_launch(void* const* d_in, const int* in_sizes, int n_in,
                              void* d_out, int out_size) {
    const float* x      = (const float*)d_in[0];
    const float* vision = (const float*)d_in[1];
    const float* ln1_g = (const float*)d_in[2];  const float* ln1_b = (const float*)d_in[3];
    const float* ln2_g = (const float*)d_in[4];  const float* ln2_b = (const float*)d_in[5];
    const float* ln3_g = (const float*)d_in[6];  const float* ln3_b = (const float*)d_in[7];
    const float* sa_wq = (const float*)d_in[8];  const float* sa_bq = (const float*)d_in[9];
    const float* sa_wk = (const float*)d_in[10]; const float* sa_bk = (const float*)d_in[11];
    const float* sa_wv = (const float*)d_in[12]; const float* sa_bv = (const float*)d_in[13];
    const float* sa_wo = (const float*)d_in[14]; const float* sa_bo = (const float*)d_in[15];
    const float* ca_wq = (const float*)d_in[16]; const float* ca_bq = (const float*)d_in[17];
    const float* ca_wk = (const float*)d_in[18]; const float* ca_bk = (const float*)d_in[19];
    const float* ca_wv = (const float*)d_in[20]; const float* ca_bv = (const float*)d_in[21];
    const float* ca_wo = (const float*)d_in[22]; const float* ca_bo = (const float*)d_in[23];
    const float* rw    = (const float*)d_in[24]; const float* rb    = (const float*)d_in[25];
    const float* ew1   = (const float*)d_in[26]; const float* eb1   = (const float*)d_in[27];
    const float* ew2   = (const float*)d_in[28]; const float* eb2   = (const float*)d_in[29];
    float* out = (float*)d_out;

    float *p_h, *p_q, *p_k, *p_v, *p_x1, *p_x2;
    __nv_bfloat16 *p_hh, *p_hl, *p_ath, *p_atl, *p_vh, *p_vl, *p_wh, *p_wl;
    cudaGetSymbolAddress((void**)&p_h,  g_h);
    cudaGetSymbolAddress((void**)&p_q,  g_q);
    cudaGetSymbolAddress((void**)&p_k,  g_k);
    cudaGetSymbolAddress((void**)&p_v,  g_v);
    cudaGetSymbolAddress((void**)&p_x1, g_x1);
    cudaGetSymbolAddress((void**)&p_x2, g_x2);
    cudaGetSymbolAddress((void**)&p_hh, g_h_hi);
    cudaGetSymbolAddress((void**)&p_hl, g_h_lo);
    cudaGetSymbolAddress((void**)&p_ath, g_att_hi);
    cudaGetSymbolAddress((void**)&p_atl, g_att_lo);
    cudaGetSymbolAddress((void**)&p_vh, g_vis_hi);
    cudaGetSymbolAddress((void**)&p_vl, g_vis_lo);
    cudaGetSymbolAddress((void**)&p_wh, g_w_hi);
    cudaGetSymbolAddress((void**)&p_wl, g_w_lo);

    const int flash_smem = FLASH_SMEM_FLOATS * (int)sizeof(float);
    const int gemm_smem  = GEMM_SMEM_BYTES;
    cudaFuncSetAttribute(flash_kernel,  cudaFuncAttributeMaxDynamicSharedMemorySize, flash_smem);
    cudaFuncSetAttribute(gemm128,       cudaFuncAttributeMaxDynamicSharedMemorySize, gemm_smem);
    cudaFuncSetAttribute(kvgemm128,     cudaFuncAttributeMaxDynamicSharedMemorySize, gemm_smem);
    cudaFuncSetAttribute(egemm1_kernel, cudaFuncAttributeMaxDynamicSharedMemorySize, gemm_smem);
    cudaFuncSetAttribute(egemm2_kernel, cudaFuncAttributeMaxDynamicSharedMemorySize, gemm_smem);

    // --- one-time (per-launch) weight + vision conversion ---
    auto conv = [&](const float* src, size_t off, int n) {
        conv_kernel<<<(n / 4 + 255) / 256, 256>>>(src, p_wh + off, p_wl + off, n);
    };
    conv(sa_wq, OFF_SAWQ, SZ_QO); conv(sa_wk, OFF_SAWK, SZ_KV);
    conv(sa_wv, OFF_SAWV, SZ_KV); conv(sa_wo, OFF_SAWO, SZ_QO);
    conv(ca_wq, OFF_CAWQ, SZ_QO); conv(ca_wk, OFF_CAWK, SZ_KV);
    conv(ca_wv, OFF_CAWV, SZ_KV); conv(ca_wo, OFF_CAWO, SZ_QO);
    conv(ew1, OFF_EW1, EE * CC * FF);
    conv(ew2, OFF_EW2, EE * FF * CC);
    conv_kernel<<<(BB * MV * CC / 4 + 255) / 256, 256>>>(vision, p_vh, p_vl, BB * MV * CC);

    dim3 gC(CC / 128, TOK / 128);
    dim3 gKVsa(2, TOK / 128);
    dim3 gKVca(2, (BB * MV) / 128);
    dim3 gAtt(NN / 128, HH, BB);

    // --- block 1: pre-norm causal GQA self-attn + residual ---
    ln_kernel<<<TOK, 256>>>(x, ln1_g, ln1_b, p_h, p_hh, p_hl);
    gemm128<<<gC, 256, gemm_smem>>>(p_hh, p_hl, OFF_SAWQ, sa_bq, nullptr, p_q, TOK, CC, CC);
    kvgemm128<<<gKVsa, 256, gemm_smem>>>(p_hh, p_hl, OFF_SAWK, sa_bk, OFF_SAWV, sa_bv, p_k, p_v, TOK, CC);
    flash_kernel<<<gAtt, 256, flash_smem>>>(p_q, p_k, p_v, p_ath, p_atl, NN, 1);
    gemm128<<<gC, 256, gemm_smem>>>(p_ath, p_atl, OFF_SAWO, sa_bo, x, p_x1, TOK, CC, CC);

    // --- block 2: pre-norm cross-attn + residual ---
    ln_kernel<<<TOK, 256>>>(p_x1, ln2_g, ln2_b, p_h, p_hh, p_hl);
    gemm128<<<gC, 256, gemm_smem>>>(p_hh, p_hl, OFF_CAWQ, ca_bq, nullptr, p_q, TOK, CC, CC);
    kvgemm128<<<gKVca, 256, gemm_smem>>>(p_vh, p_vl, OFF_CAWK, ca_bk, OFF_CAWV, ca_bv, p_k, p_v, BB * MV, CC);
    flash_kernel<<<gAtt, 256, flash_smem>>>(p_q, p_k, p_v, p_ath, p_atl, MV, 0);
    gemm128<<<gC, 256, gemm_smem>>>(p_ath, p_atl, OFF_CAWO, ca_bo, p_x1, p_x2, TOK, CC, CC);

    // --- block 3: pre-norm MoE + residual ---
    ln_kernel<<<TOK, 256>>>(p_x2, ln3_g, ln3_b, p_h, p_hh, p_hl);
    zero_kernel<<<1, 32>>>();
    router_kernel<<<TOK / 256, 256>>>(rw, rb);
    egemm1_kernel<<<dim3(FF / 128, EROWS / 128, EE), 256, gemm_smem>>>(eb1);
    egemm2_kernel<<<dim3(CC / 128, EROWS / 128, EE), 256, gemm_smem>>>(eb2);
    combine_kernel<<<TOK, 128>>>(out);
    aux_kernel<<<1, 1>>>(out, out_size);
}

// round 8
// speedup vs baseline: 1.6134x; 1.1867x over previous
#include <cuda_runtime.h>
#include <cuda_bf16.h>
#include <mma.h>
#include <math.h>

using namespace nvcuda;

// ---------------- problem constants ----------------
#define BB 4
#define NN 2048
#define MV 576
#define CC 512
#define HH 8
#define KVH 2
#define DD 64
#define EE 8
#define TOPK 2
#define FF 2048
#define TOK (BB*NN)
#define KVDIM (KVH*DD)       // 128
#define EROWS 8192

// weight buffer offsets (elements)
#define SZ_QO (CC*CC)
#define SZ_KV (CC*KVDIM)
#define OFF_SAWQ 0
#define OFF_SAWK (OFF_SAWQ+SZ_QO)
#define OFF_SAWV (OFF_SAWK+SZ_KV)
#define OFF_SAWO (OFF_SAWV+SZ_KV)
#define OFF_CAWQ (OFF_SAWO+SZ_QO)
#define OFF_CAWK (OFF_CAWQ+SZ_QO)
#define OFF_CAWV (OFF_CAWK+SZ_KV)
#define OFF_CAWO (OFF_CAWV+SZ_KV)
#define OFF_EW1  (OFF_CAWO+SZ_QO)
#define OFF_EW2  (OFF_EW1 + (size_t)EE*CC*FF)
#define WTOT     (OFF_EW2 + (size_t)EE*FF*CC)

// ---------------- static scratch ----------------
__device__ float g_h  [(size_t)TOK*CC];     // fp32 LN out (router)
__device__ float g_x1 [(size_t)TOK*CC];
__device__ float g_x2 [(size_t)TOK*CC];
__device__ float g_eo [(size_t)EE*EROWS*CC];
__device__ __nv_bfloat16 g_h_hi [(size_t)TOK*CC];
__device__ __nv_bfloat16 g_h_lo [(size_t)TOK*CC];
__device__ __nv_bfloat16 g_q_hi [(size_t)TOK*CC];
__device__ __nv_bfloat16 g_q_lo [(size_t)TOK*CC];
__device__ __nv_bfloat16 g_k_hi [(size_t)TOK*KVDIM];
__device__ __nv_bfloat16 g_k_lo [(size_t)TOK*KVDIM];
__device__ __nv_bfloat16 g_v_hi [(size_t)TOK*KVDIM];
__device__ __nv_bfloat16 g_v_lo [(size_t)TOK*KVDIM];
__device__ __nv_bfloat16 g_att_hi[(size_t)TOK*CC];
__device__ __nv_bfloat16 g_att_lo[(size_t)TOK*CC];
__device__ __nv_bfloat16 g_vis_hi[(size_t)BB*MV*CC];
__device__ __nv_bfloat16 g_vis_lo[(size_t)BB*MV*CC];
__device__ __nv_bfloat16 g_mid_hi[(size_t)EE*EROWS*FF];
__device__ __nv_bfloat16 g_mid_lo[(size_t)EE*EROWS*FF];
__device__ __nv_bfloat16 g_w_hi[WTOT];
__device__ __nv_bfloat16 g_w_lo[WTOT];
__device__ int   g_count[EE];
__device__ float g_Psum[EE];
__device__ int   g_tokrow [TOK*TOPK];
__device__ float g_tokgate[TOK*TOPK];
__device__ int   g_tok_of_row[EE*EROWS];

// ---------------- helpers ----------------
__device__ __forceinline__ void split1(float v, __nv_bfloat16& h, __nv_bfloat16& l) {
    h = __float2bfloat16(v);
    l = __float2bfloat16(v - __bfloat162float(h));
}
// pack 2 floats -> bf16x2 register: lo -> bits[0:16), hi -> bits[16:32)
__device__ __forceinline__ unsigned pk2(float lo, float hi) {
    unsigned r;
    asm("cvt.rn.bf16x2.f32 %0, %1, %2;" : "=r"(r) : "f"(hi), "f"(lo));
    return r;
}
__device__ __forceinline__ float bfrt(float x) {   // bf16 round-trip
    return __bfloat162float(__float2bfloat16(x));
}
__device__ __forceinline__ void mma16816(float* c, const unsigned* a, const unsigned* b) {
    asm volatile(
        "mma.sync.aligned.m16n8k16.row.col.f32.bf16.bf16.f32 "
        "{%0,%1,%2,%3},{%4,%5,%6,%7},{%8,%9},{%0,%1,%2,%3};"
        : "+f"(c[0]), "+f"(c[1]), "+f"(c[2]), "+f"(c[3])
        : "r"(a[0]), "r"(a[1]), "r"(a[2]), "r"(a[3]), "r"(b[0]), "r"(b[1]));
}

// ---------------- fp32 -> hi/lo bf16 conversion ----------------
__global__ void conv_kernel(const float* __restrict__ src, __nv_bfloat16* __restrict__ hi,
                            __nv_bfloat16* __restrict__ lo, int n) {
    int i = (blockIdx.x * blockDim.x + threadIdx.x) * 4;
    if (i >= n) return;
    float4 v = *(const float4*)(src + i);
    __align__(8) __nv_bfloat16 h[4], l[4];
    split1(v.x, h[0], l[0]); split1(v.y, h[1], l[1]);
    split1(v.z, h[2], l[2]); split1(v.w, h[3], l[3]);
    *(uint2*)(hi + i) = *(uint2*)h;
    *(uint2*)(lo + i) = *(uint2*)l;
}

// ---------------- LayerNorm (fp32 + hi/lo bf16 out) ----------------
__global__ void ln_kernel(const float* __restrict__ x, const float* __restrict__ g,
                          const float* __restrict__ b, float* __restrict__ o,
                          __nv_bfloat16* __restrict__ ohi, __nv_bfloat16* __restrict__ olo) {
    int t = blockIdx.x;
    int tid = threadIdx.x;
    const float* xr = x + (size_t)t * CC;
    float v0 = xr[tid], v1 = xr[tid + 256];
    __shared__ float red[256];
    red[tid] = v0 + v1; __syncthreads();
    for (int off = 128; off > 0; off >>= 1) {
        if (tid < off) red[tid] += red[tid + off];
        __syncthreads();
    }
    float mu = red[0] * (1.0f / CC);
    __syncthreads();
    float d0 = v0 - mu, d1 = v1 - mu;
    red[tid] = d0 * d0 + d1 * d1; __syncthreads();
    for (int off = 128; off > 0; off >>= 1) {
        if (tid < off) red[tid] += red[tid + off];
        __syncthreads();
    }
    float rstd = rsqrtf(red[0] * (1.0f / CC) + 1e-6f);
    size_t base = (size_t)t * CC;
    float r0 = d0 * rstd * g[tid]       + b[tid];
    float r1 = d1 * rstd * g[tid + 256] + b[tid + 256];
    o[base + tid] = r0; o[base + tid + 256] = r1;
    __nv_bfloat16 h, l;
    split1(r0, h, l); ohi[base + tid] = h;       olo[base + tid] = l;
    split1(r1, h, l); ohi[base + tid + 256] = h; olo[base + tid + 256] = l;
}

// ---------------- wmma split-bf16 GEMM core (unchanged from R7) ----------------
#define APAD 40
#define BPAD 136
#define CPAD 132
struct SmemGemm {
    __nv_bfloat16 Ah[128][APAD];
    __nv_bfloat16 Al[128][APAD];
    __nv_bfloat16 Bh[32][BPAD];
    __nv_bfloat16 Bl[32][BPAD];
};
#define GEMM_SMEM_BYTES (128*CPAD*4)

typedef wmma::fragment<wmma::accumulator, 16, 16, 16, float> AccFrag;

__device__ __forceinline__ void wmma_core(
        const __nv_bfloat16* __restrict__ Ahg, const __nv_bfloat16* __restrict__ Alg,
        const __nv_bfloat16* __restrict__ Bhg, const __nv_bfloat16* __restrict__ Blg,
        const int* __restrict__ tokidx,
        int Mr, int Nc, int Kd, int row0, int col0,
        SmemGemm* S, AccFrag (&acc)[2][4]) {
    int tid = threadIdx.x;
    int w = tid >> 5, wm = w & 3, wn = w >> 2;
    const uint4 z4 = make_uint4(0u, 0u, 0u, 0u);
    int ra = tid >> 1, kc = (tid & 1) * 16;
    int rb = tid >> 3, cb = (tid & 7) * 16;
    #pragma unroll 1
    for (int k0 = 0; k0 < Kd; k0 += 32) {
        size_t abase; bool valid;
        if (tokidx) {
            int tok = tokidx[ra];
            valid = (tok >= 0);
            abase = (size_t)(valid ? tok : 0) * Kd + k0 + kc;
        } else {
            int gr = row0 + ra;
            valid = (gr < Mr);
            abase = (size_t)(valid ? gr : 0) * Kd + k0 + kc;
        }
        uint4 a0 = valid ? *(const uint4*)(Ahg + abase) : z4;
        uint4 a1 = valid ? *(const uint4*)(Ahg + abase + 8) : z4;
        uint4 a2 = valid ? *(const uint4*)(Alg + abase) : z4;
        uint4 a3 = valid ? *(const uint4*)(Alg + abase + 8) : z4;
        *(uint4*)&S->Ah[ra][kc]     = a0;
        *(uint4*)&S->Ah[ra][kc + 8] = a1;
        *(uint4*)&S->Al[ra][kc]     = a2;
        *(uint4*)&S->Al[ra][kc + 8] = a3;
        size_t bbase = (size_t)(k0 + rb) * Nc + col0 + cb;
        uint4 b0 = *(const uint4*)(Bhg + bbase);
        uint4 b1 = *(const uint4*)(Bhg + bbase + 8);
        uint4 b2 = *(const uint4*)(Blg + bbase);
        uint4 b3 = *(const uint4*)(Blg + bbase + 8);
        *(uint4*)&S->Bh[rb][cb]     = b0;
        *(uint4*)&S->Bh[rb][cb + 8] = b1;
        *(uint4*)&S->Bl[rb][cb]     = b2;
        *(uint4*)&S->Bl[rb][cb + 8] = b3;
        __syncthreads();
        #pragma unroll
        for (int ks = 0; ks < 2; ks++) {
            wmma::fragment<wmma::matrix_a, 16,16,16, __nv_bfloat16, wmma::row_major> ah[2], al[2];
            wmma::fragment<wmma::matrix_b, 16,16,16, __nv_bfloat16, wmma::row_major> bh[4], bl[4];
            #pragma unroll
            for (int i = 0; i < 2; i++) {
                wmma::load_matrix_sync(ah[i], &S->Ah[wm*32 + i*16][ks*16], APAD);
                wmma::load_matrix_sync(al[i], &S->Al[wm*32 + i*16][ks*16], APAD);
            }
            #pragma unroll
            for (int j = 0; j < 4; j++) {
                wmma::load_matrix_sync(bh[j], &S->Bh[ks*16][wn*64 + j*16], BPAD);
                wmma::load_matrix_sync(bl[j], &S->Bl[ks*16][wn*64 + j*16], BPAD);
            }
            #pragma unroll
            for (int i = 0; i < 2; i++)
                #pragma unroll
                for (int j = 0; j < 4; j++) {
                    wmma::mma_sync(acc[i][j], ah[i], bh[j], acc[i][j]);
                    wmma::mma_sync(acc[i][j], ah[i], bl[j], acc[i][j]);
                    wmma::mma_sync(acc[i][j], al[i], bh[j], acc[i][j]);
                }
        }
        __syncthreads();
    }
}

__device__ __forceinline__ void stage_acc(AccFrag (&acc)[2][4], float (*Cs)[CPAD], int tid) {
    int w = tid >> 5, wm = w & 3, wn = w >> 2;
    #pragma unroll
    for (int i = 0; i < 2; i++)
        #pragma unroll
        for (int j = 0; j < 4; j++)
            wmma::store_matrix_sync(&Cs[wm*32 + i*16][wn*64 + j*16], acc[i][j],
                                    CPAD, wmma::mem_row_major);
    __syncthreads();
}

// ---------------- generic GEMM: fp32 out (bias/resid) OR hi/lo bf16 out ----------------
__global__ void __launch_bounds__(256) gemm128(
        const __nv_bfloat16* __restrict__ Ahg, const __nv_bfloat16* __restrict__ Alg,
        int woff, const float* __restrict__ bias, const float* __restrict__ resid,
        float* __restrict__ out,
        __nv_bfloat16* __restrict__ ohi, __nv_bfloat16* __restrict__ olo,
        int Mr, int Nc, int Kd) {
    extern __shared__ char smraw[];
    SmemGemm* S = (SmemGemm*)smraw;
    float (*Cs)[CPAD] = (float(*)[CPAD])smraw;
    int tid = threadIdx.x;
    int row0 = blockIdx.y * 128, col0 = blockIdx.x * 128;
    AccFrag acc[2][4];
    #pragma unroll
    for (int i = 0; i < 2; i++)
        #pragma unroll
        for (int j = 0; j < 4; j++) wmma::fill_fragment(acc[i][j], 0.0f);
    wmma_core(Ahg, Alg, g_w_hi + woff, g_w_lo + woff, nullptr, Mr, Nc, Kd, row0, col0, S, acc);
    stage_acc(acc, Cs, tid);
    #pragma unroll
    for (int u = 0; u < 16; u++) {
        int f = tid + u * 256;
        int r = f >> 5, c = (f & 31) * 4;
        int gr = row0 + r;
        if (gr >= Mr) continue;
        int gc = col0 + c;
        float4 v = *(float4*)&Cs[r][c];
        if (bias) { v.x += bias[gc]; v.y += bias[gc+1]; v.z += bias[gc+2]; v.w += bias[gc+3]; }
        if (resid) {
            float4 rr = *(const float4*)(resid + (size_t)gr * Nc + gc);
            v.x += rr.x; v.y += rr.y; v.z += rr.z; v.w += rr.w;
        }
        if (out) {
            *(float4*)(out + (size_t)gr * Nc + gc) = v;
        } else {
            __align__(8) __nv_bfloat16 hh[4], ll[4];
            split1(v.x, hh[0], ll[0]); split1(v.y, hh[1], ll[1]);
            split1(v.z, hh[2], ll[2]); split1(v.w, hh[3], ll[3]);
            *(uint2*)(ohi + (size_t)gr * Nc + gc) = *(uint2*)hh;
            *(uint2*)(olo + (size_t)gr * Nc + gc) = *(uint2*)ll;
        }
    }
}

// ---------------- fused K+V projection -> hi/lo bf16 ----------------
__global__ void __launch_bounds__(256) kvgemm128(
        const __nv_bfloat16* __restrict__ Ahg, const __nv_bfloat16* __restrict__ Alg,
        int woffk, const float* __restrict__ bk,
        int woffv, const float* __restrict__ bv,
        __nv_bfloat16* __restrict__ okh, __nv_bfloat16* __restrict__ okl,
        __nv_bfloat16* __restrict__ ovh, __nv_bfloat16* __restrict__ ovl,
        int Mr, int Kd) {
    extern __shared__ char smraw[];
    SmemGemm* S = (SmemGemm*)smraw;
    float (*Cs)[CPAD] = (float(*)[CPAD])smraw;
    int woff          = (blockIdx.x == 0) ? woffk : woffv;
    const float* bias = (blockIdx.x == 0) ? bk : bv;
    __nv_bfloat16* oh = (blockIdx.x == 0) ? okh : ovh;
    __nv_bfloat16* ol = (blockIdx.x == 0) ? okl : ovl;
    int tid = threadIdx.x;
    int row0 = blockIdx.y * 128;
    AccFrag acc[2][4];
    #pragma unroll
    for (int i = 0; i < 2; i++)
        #pragma unroll
        for (int j = 0; j < 4; j++) wmma::fill_fragment(acc[i][j], 0.0f);
    wmma_core(Ahg, Alg, g_w_hi + woff, g_w_lo + woff, nullptr, Mr, KVDIM, Kd, row0, 0, S, acc);
    stage_acc(acc, Cs, tid);
    #pragma unroll
    for (int u = 0; u < 16; u++) {
        int f = tid + u * 256;
        int r = f >> 5, c = (f & 31) * 4;
        int gr = row0 + r;
        if (gr >= Mr) continue;
        float4 v = *(float4*)&Cs[r][c];
        v.x += bias[c]; v.y += bias[c+1]; v.z += bias[c+2]; v.w += bias[c+3];
        __align__(8) __nv_bfloat16 hh[4], ll[4];
        split1(v.x, hh[0], ll[0]); split1(v.y, hh[1], ll[1]);
        split1(v.z, hh[2], ll[2]); split1(v.w, hh[3], ll[3]);
        *(uint2*)(oh + (size_t)gr * KVDIM + c) = *(uint2*)hh;
        *(uint2*)(ol + (size_t)gr * KVDIM + c) = *(uint2*)ll;
    }
}

// ---------------- FA2 flash attention: mma.m16n8k16 split-bf16 ----------------
#define KPAD 72   // word stride 36 == 4 (mod 32): B-frag loads conflict-free
__global__ void __launch_bounds__(256) flash_mma(
        const __nv_bfloat16* __restrict__ qhi, const __nv_bfloat16* __restrict__ qlo,
        const __nv_bfloat16* __restrict__ khi, const __nv_bfloat16* __restrict__ klo,
        const __nv_bfloat16* __restrict__ vhi, const __nv_bfloat16* __restrict__ vlo,
        __nv_bfloat16* __restrict__ ohi, __nv_bfloat16* __restrict__ olo,
        int n_kv, int causal) {
    __shared__ __nv_bfloat16 Kh[64][KPAD], Kl[64][KPAD], Vth[64][KPAD], Vtl[64][KPAD];
    int qt = blockIdx.x, h = blockIdx.y, b = blockIdx.z;
    int g = h >> 2;
    int tid = threadIdx.x, w = tid >> 5, lane = tid & 31;
    int r0 = lane >> 2, tq = lane & 3;
    int qrow = qt * 128 + w * 16 + r0;                   // local q row (first of pair)

    // Q fragments (loaded once from global): 4 k-steps x {a0..a3}, hi and lo
    unsigned qah[4][4], qal[4][4];
    {
        const __nv_bfloat16* q0h = qhi + ((size_t)(b * NN + qrow)) * CC + h * DD;
        const __nv_bfloat16* q1h = qhi + ((size_t)(b * NN + qrow + 8)) * CC + h * DD;
        const __nv_bfloat16* q0l = qlo + ((size_t)(b * NN + qrow)) * CC + h * DD;
        const __nv_bfloat16* q1l = qlo + ((size_t)(b * NN + qrow + 8)) * CC + h * DD;
        #pragma unroll
        for (int ks = 0; ks < 4; ks++) {
            int c = ks * 16 + tq * 2;
            qah[ks][0] = *(const unsigned*)(q0h + c);
            qah[ks][1] = *(const unsigned*)(q1h + c);
            qah[ks][2] = *(const unsigned*)(q0h + c + 8);
            qah[ks][3] = *(const unsigned*)(q1h + c + 8);
            qal[ks][0] = *(const unsigned*)(q0l + c);
            qal[ks][1] = *(const unsigned*)(q1l + c);
            qal[ks][2] = *(const unsigned*)(q0l + c + 8);
            qal[ks][3] = *(const unsigned*)(q1l + c + 8);
        }
    }

    float m0 = -1e30f, m1 = -1e30f, l0 = 0.0f, l1 = 0.0f;
    float o[8][4] = {};

    int key_l = tid >> 2, dseg = (tid & 3) * 16;         // smem fill mapping
    int nkt = causal ? (2 * qt + 2) : (n_kv / 64);
    for (int kt = 0; kt < nkt; kt++) {
        __syncthreads();
        {   // fill K (row-major) and V^T
            size_t base = ((size_t)(b * n_kv + kt * 64 + key_l)) * KVDIM + g * DD + dseg;
            *(uint4*)&Kh[key_l][dseg]     = *(const uint4*)(khi + base);
            *(uint4*)&Kh[key_l][dseg + 8] = *(const uint4*)(khi + base + 8);
            *(uint4*)&Kl[key_l][dseg]     = *(const uint4*)(klo + base);
            *(uint4*)&Kl[key_l][dseg + 8] = *(const uint4*)(klo + base + 8);
            const __nv_bfloat16* vh = vhi + base;
            const __nv_bfloat16* vl = vlo + base;
            #pragma unroll
            for (int i = 0; i < 16; i++) {
                Vth[dseg + i][key_l] = vh[i];
                Vtl[dseg + i][key_l] = vl[i];
            }
        }
        __syncthreads();

        // ---- S = Q @ K^T ----
        float sc[8][4] = {};
        #pragma unroll
        for (int nt = 0; nt < 8; nt++) {
            int krow = nt * 8 + r0;
            #pragma unroll
            for (int ks = 0; ks < 4; ks++) {
                int c = ks * 16 + tq * 2;
                unsigned bh[2], bl[2];
                bh[0] = *(const unsigned*)&Kh[krow][c];
                bh[1] = *(const unsigned*)&Kh[krow][c + 8];
                bl[0] = *(const unsigned*)&Kl[krow][c];
                bl[1] = *(const unsigned*)&Kl[krow][c + 8];
                mma16816(sc[nt], qah[ks], bh);
                mma16816(sc[nt], qah[ks], bl);
                mma16816(sc[nt], qal[ks], bh);
            }
        }
        // ---- scale + mask ----
        bool maskit = causal && (kt >= 2 * qt);
        #pragma unroll
        for (int nt = 0; nt < 8; nt++) {
            #pragma unroll
            for (int j = 0; j < 4; j++) {
                float v = sc[nt][j] * 0.125f;
                if (maskit) {
                    int col = kt * 64 + nt * 8 + tq * 2 + (j & 1);
                    int row = qt * 128 + w * 16 + r0 + ((j >> 1) ? 8 : 0);
                    if (col > row) v = -1e9f;
                }
                sc[nt][j] = v;
            }
        }
        // ---- online softmax (rows r0 and r0+8, quad reduce) ----
        float rm0 = -1e30f, rm1 = -1e30f;
        #pragma unroll
        for (int nt = 0; nt < 8; nt++) {
            rm0 = fmaxf(rm0, fmaxf(sc[nt][0], sc[nt][1]));
            rm1 = fmaxf(rm1, fmaxf(sc[nt][2], sc[nt][3]));
        }
        #pragma unroll
        for (int off = 1; off < 4; off <<= 1) {
            rm0 = fmaxf(rm0, __shfl_xor_sync(0xffffffffu, rm0, off));
            rm1 = fmaxf(rm1, __shfl_xor_sync(0xffffffffu, rm1, off));
        }
        float mn0 = fmaxf(m0, rm0), mn1 = fmaxf(m1, rm1);
        float al0 = __expf(m0 - mn0), al1 = __expf(m1 - mn1);
        m0 = mn0; m1 = mn1;
        float rs0 = 0.0f, rs1 = 0.0f;
        #pragma unroll
        for (int nt = 0; nt < 8; nt++) {
            sc[nt][0] = __expf(sc[nt][0] - mn0);
            sc[nt][1] = __expf(sc[nt][1] - mn0);
            sc[nt][2] = __expf(sc[nt][2] - mn1);
            sc[nt][3] = __expf(sc[nt][3] - mn1);
            rs0 += sc[nt][0] + sc[nt][1];
            rs1 += sc[nt][2] + sc[nt][3];
        }
        #pragma unroll
        for (int off = 1; off < 4; off <<= 1) {
            rs0 += __shfl_xor_sync(0xffffffffu, rs0, off);
            rs1 += __shfl_xor_sync(0xffffffffu, rs1, off);
        }
        l0 = l0 * al0 + rs0;
        l1 = l1 * al1 + rs1;
        #pragma unroll
        for (int nt = 0; nt < 8; nt++) {
            o[nt][0] *= al0; o[nt][1] *= al0;
            o[nt][2] *= al1; o[nt][3] *= al1;
        }
        // ---- O += P @ V ----
        #pragma unroll
        for (int kp = 0; kp < 4; kp++) {
            // repack P (C-frag layout of tiles 2kp, 2kp+1 == A-frag layout)
            unsigned pah[4], pal[4];
            {
                float x0 = sc[2*kp][0],   x1 = sc[2*kp][1];
                float x2 = sc[2*kp][2],   x3 = sc[2*kp][3];
                float y0 = sc[2*kp+1][0], y1 = sc[2*kp+1][1];
                float y2 = sc[2*kp+1][2], y3 = sc[2*kp+1][3];
                pah[0] = pk2(x0, x1); pah[1] = pk2(x2, x3);
                pah[2] = pk2(y0, y1); pah[3] = pk2(y2, y3);
                pal[0] = pk2(x0 - bfrt(x0), x1 - bfrt(x1));
                pal[1] = pk2(x2 - bfrt(x2), x3 - bfrt(x3));
                pal[2] = pk2(y0 - bfrt(y0), y1 - bfrt(y1));
                pal[3] = pk2(y2 - bfrt(y2), y3 - bfrt(y3));
            }
            #pragma unroll
            for (int nt = 0; nt < 8; nt++) {
                int drow = nt * 8 + r0;
                int c = kp * 16 + tq * 2;
                unsigned bh[2], bl[2];
                bh[0] = *(const unsigned*)&Vth[drow][c];
                bh[1] = *(const unsigned*)&Vth[drow][c + 8];
                bl[0] = *(const unsigned*)&Vtl[drow][c];
                bl[1] = *(const unsigned*)&Vtl[drow][c + 8];
                mma16816(o[nt], pah, bh);
                mma16816(o[nt], pah, bl);
                mma16816(o[nt], pal, bh);
            }
        }
    }
    // ---- epilogue ----
    float inv0 = 1.0f / l0, inv1 = 1.0f / l1;
    size_t base0 = ((size_t)(b * NN + qrow)) * CC + h * DD;
    size_t base1 = ((size_t)(b * NN + qrow + 8)) * CC + h * DD;
    #pragma unroll
    for (int nt = 0; nt < 8; nt++) {
        int d = nt * 8 + tq * 2;
        float v0 = o[nt][0] * inv0, v1 = o[nt][1] * inv0;
        float v2 = o[nt][2] * inv1, v3 = o[nt][3] * inv1;
        *(unsigned*)(ohi + base0 + d) = pk2(bfrt(v0), bfrt(v1));
        *(unsigned*)(olo + base0 + d) = pk2(v0 - bfrt(v0), v1 - bfrt(v1));
        *(unsigned*)(ohi + base1 + d) = pk2(bfrt(v2), bfrt(v3));
        *(unsigned*)(olo + base1 + d) = pk2(v2 - bfrt(v2), v3 - bfrt(v3));
    }
}

// ---------------- MoE routing ----------------
__global__ void zero_kernel() {
    int t = threadIdx.x;
    if (t < EE) { g_count[t] = 0; g_Psum[t] = 0.0f; }
}

__global__ void router_kernel(const float* __restrict__ rw, const float* __restrict__ rb) {
    __shared__ float sP[EE];
    int tid = threadIdx.x;
    if (tid < EE) sP[tid] = 0.0f;
    __syncthreads();
    int t = blockIdx.x * blockDim.x + tid;
    float logit[EE];
    const float* hrow = g_h + (size_t)t * CC;
    #pragma unroll
    for (int e = 0; e < EE; e++) logit[e] = rb[e];
    for (int k = 0; k < CC; k++) {
        float hv = hrow[k];
        const float* wr = rw + k * EE;
        #pragma unroll
        for (int e = 0; e < EE; e++) logit[e] += hv * wr[e];
    }
    float mx = logit[0];
    #pragma unroll
    for (int e = 1; e < EE; e++) mx = fmaxf(mx, logit[e]);
    float p[EE], ps = 0.0f;
    #pragma unroll
    for (int e = 0; e < EE; e++) { p[e] = __expf(logit[e] - mx); ps += p[e]; }
    float invs = 1.0f / ps;
    #pragma unroll
    for (int e = 0; e < EE; e++) p[e] *= invs;
    int i0 = 0;
    #pragma unroll
    for (int e = 1; e < EE; e++) if (p[e] > p[i0]) i0 = e;
    int i1 = (i0 == 0) ? 1 : 0;
    #pragma unroll
    for (int e = 0; e < EE; e++) if (e != i0 && p[e] > p[i1]) i1 = e;
    float gs = p[i0] + p[i1];
    float g0 = p[i0] / gs, g1 = p[i1] / gs;
    int s0 = atomicAdd(&g_count[i0], 1);
    int s1 = atomicAdd(&g_count[i1], 1);
    int r0 = i0 * EROWS + s0, r1 = i1 * EROWS + s1;
    g_tok_of_row[r0] = t; g_tok_of_row[r1] = t;
    g_tokrow[t * 2] = r0; g_tokrow[t * 2 + 1] = r1;
    g_tokgate[t * 2] = g0; g_tokgate[t * 2 + 1] = g1;
    #pragma unroll
    for (int e = 0; e < EE; e++) atomicAdd(&sP[e], p[e]);
    __syncthreads();
    if (tid < EE) atomicAdd(&g_Psum[tid], sP[tid]);
}

// ---------------- expert GEMM 1 (gathered A, GELU -> mid hi/lo) ----------------
__global__ void __launch_bounds__(256) egemm1_kernel(const float* __restrict__ eb1) {
    int e = blockIdx.z;
    int cnt = g_count[e];
    int row0 = blockIdx.y * 128;
    if (row0 >= cnt) return;
    int col0 = blockIdx.x * 128;
    extern __shared__ char smraw[];
    SmemGemm* S = (SmemGemm*)smraw;
    float (*Cs)[CPAD] = (float(*)[CPAD])smraw;
    __shared__ int s_tok[128];
    int tid = threadIdx.x;
    if (tid < 128) {
        int gr = row0 + tid;
        s_tok[tid] = (gr < cnt) ? g_tok_of_row[e * EROWS + gr] : -1;
    }
    __syncthreads();
    AccFrag acc[2][4];
    #pragma unroll
    for (int i = 0; i < 2; i++)
        #pragma unroll
        for (int j = 0; j < 4; j++) wmma::fill_fragment(acc[i][j], 0.0f);
    size_t woff = OFF_EW1 + (size_t)e * CC * FF;
    wmma_core(g_h_hi, g_h_lo, g_w_hi + woff, g_w_lo + woff, s_tok, 0, FF, CC, 0, col0, S, acc);
    stage_acc(acc, Cs, tid);
    #pragma unroll
    for (int u = 0; u < 16; u++) {
        int f = tid + u * 256;
        int r = f >> 5, c = (f & 31) * 4;
        if (row0 + r >= cnt) continue;
        int gc = col0 + c;
        float4 v = *(float4*)&Cs[r][c];
        float vv[4] = {v.x, v.y, v.z, v.w};
        __align__(8) __nv_bfloat16 hh[4], ll[4];
        #pragma unroll
        for (int j = 0; j < 4; j++) {
            float xx = vv[j] + eb1[e * FF + gc + j];
            float uu = 0.7978845608028654f * (xx + 0.044715f * xx * xx * xx);
            float ge = 0.5f * xx * (1.0f + tanhf(uu));
            split1(ge, hh[j], ll[j]);
        }
        size_t idx = ((size_t)e * EROWS + row0 + r) * FF + gc;
        *(uint2*)(g_mid_hi + idx) = *(uint2*)hh;
        *(uint2*)(g_mid_lo + idx) = *(uint2*)ll;
    }
}

// ---------------- expert GEMM 2 ----------------
__global__ void __launch_bounds__(256) egemm2_kernel(const float* __restrict__ eb2) {
    int e = blockIdx.z;
    int cnt = g_count[e];
    int row0 = blockIdx.y * 128;
    if (row0 >= cnt) return;
    int col0 = blockIdx.x * 128;
    extern __shared__ char smraw[];
    SmemGemm* S = (SmemGemm*)smraw;
    float (*Cs)[CPAD] = (float(*)[CPAD])smraw;
    int tid = threadIdx.x;
    AccFrag acc[2][4];
    #pragma unroll
    for (int i = 0; i < 2; i++)
        #pragma unroll
        for (int j = 0; j < 4; j++) wmma::fill_fragment(acc[i][j], 0.0f);
    size_t woff = OFF_EW2 + (size_t)e * FF * CC;
    wmma_core(g_mid_hi + (size_t)e * EROWS * FF, g_mid_lo + (size_t)e * EROWS * FF,
              g_w_hi + woff, g_w_lo + woff, nullptr, cnt, CC, FF, row0, col0, S, acc);
    stage_acc(acc, Cs, tid);
    #pragma unroll
    for (int u = 0; u < 16; u++) {
        int f = tid + u * 256;
        int r = f >> 5, c = (f & 31) * 4;
        if (row0 + r >= cnt) continue;
        int gc = col0 + c;
        float4 v = *(float4*)&Cs[r][c];
        v.x += eb2[e * CC + gc];     v.y += eb2[e * CC + gc + 1];
        v.z += eb2[e * CC + gc + 2]; v.w += eb2[e * CC + gc + 3];
        *(float4*)&g_eo[((size_t)e * EROWS + row0 + r) * CC + gc] = v;
    }
}

// ---------------- combine + aux ----------------
__global__ void combine_kernel(float* __restrict__ out) {
    int t = blockIdx.x;
    int tid = threadIdx.x;
    int r0 = g_tokrow[t * 2], r1 = g_tokrow[t * 2 + 1];
    float g0 = g_tokgate[t * 2], g1 = g_tokgate[t * 2 + 1];
    const float* x2 = g_x2 + (size_t)t * CC;
    const float* e0 = g_eo + (size_t)r0 * CC;
    const float* e1 = g_eo + (size_t)r1 * CC;
    float* orow = out + (size_t)t * CC;
    for (int c = tid; c < CC; c += 128)
        orow[c] = x2[c] + g0 * e0[c] + g1 * e1[c];
}

__global__ void aux_kernel(float* __restrict__ out, int out_size) {
    if (threadIdx.x == 0 && blockIdx.x == 0) {
        float a = 0.0f;
        for (int e = 0; e < EE; e++)
            a += (g_count[e] / (float)TOK) * (g_Psum[e] / (float)TOK);
        a *= (float)EE;
        if (out_size > TOK * CC) out[TOK * CC] = a;
    }
}

// ---------------- launch ----------------
extern "C" void kernel_launch(void* const* d_in, const int* in_sizes, int n_in,
                              void* d_out, int out_size) {
    const float* x      = (const float*)d_in[0];
    const float* vision = (const float*)d_in[1];
    const float* ln1_g = (const float*)d_in[2];  const float* ln1_b = (const float*)d_in[3];
    const float* ln2_g = (const float*)d_in[4];  const float* ln2_b = (const float*)d_in[5];
    const float* ln3_g = (const float*)d_in[6];  const float* ln3_b = (const float*)d_in[7];
    const float* sa_wq = (const float*)d_in[8];  const float* sa_bq = (const float*)d_in[9];
    const float* sa_wk = (const float*)d_in[10]; const float* sa_bk = (const float*)d_in[11];
    const float* sa_wv = (const float*)d_in[12]; const float* sa_bv = (const float*)d_in[13];
    const float* sa_wo = (const float*)d_in[14]; const float* sa_bo = (const float*)d_in[15];
    const float* ca_wq = (const float*)d_in[16]; const float* ca_bq = (const float*)d_in[17];
    const float* ca_wk = (const float*)d_in[18]; const float* ca_bk = (const float*)d_in[19];
    const float* ca_wv = (const float*)d_in[20]; const float* ca_bv = (const float*)d_in[21];
    const float* ca_wo = (const float*)d_in[22]; const float* ca_bo = (const float*)d_in[23];
    const float* rw    = (const float*)d_in[24]; const float* rb    = (const float*)d_in[25];
    const float* ew1   = (const float*)d_in[26]; const float* eb1   = (const float*)d_in[27];
    const float* ew2   = (const float*)d_in[28]; const float* eb2   = (const float*)d_in[29];
    float* out = (float*)d_out;

    float *p_h, *p_x1, *p_x2;
    __nv_bfloat16 *p_hh, *p_hl, *p_qh, *p_ql, *p_kh, *p_kl, *p_vh_, *p_vl_;
    __nv_bfloat16 *p_ath, *p_atl, *p_vih, *p_vil, *p_wh, *p_wl;
    cudaGetSymbolAddress((void**)&p_h,  g_h);
    cudaGetSymbolAddress((void**)&p_x1, g_x1);
    cudaGetSymbolAddress((void**)&p_x2, g_x2);
    cudaGetSymbolAddress((void**)&p_hh, g_h_hi);
    cudaGetSymbolAddress((void**)&p_hl, g_h_lo);
    cudaGetSymbolAddress((void**)&p_qh, g_q_hi);
    cudaGetSymbolAddress((void**)&p_ql, g_q_lo);
    cudaGetSymbolAddress((void**)&p_kh, g_k_hi);
    cudaGetSymbolAddress((void**)&p_kl, g_k_lo);
    cudaGetSymbolAddress((void**)&p_vh_, g_v_hi);
    cudaGetSymbolAddress((void**)&p_vl_, g_v_lo);
    cudaGetSymbolAddress((void**)&p_ath, g_att_hi);
    cudaGetSymbolAddress((void**)&p_atl, g_att_lo);
    cudaGetSymbolAddress((void**)&p_vih, g_vis_hi);
    cudaGetSymbolAddress((void**)&p_vil, g_vis_lo);
    cudaGetSymbolAddress((void**)&p_wh, g_w_hi);
    cudaGetSymbolAddress((void**)&p_wl, g_w_lo);

    const int gemm_smem = GEMM_SMEM_BYTES;
    cudaFuncSetAttribute(gemm128,       cudaFuncAttributeMaxDynamicSharedMemorySize, gemm_smem);
    cudaFuncSetAttribute(kvgemm128,     cudaFuncAttributeMaxDynamicSharedMemorySize, gemm_smem);
    cudaFuncSetAttribute(egemm1_kernel, cudaFuncAttributeMaxDynamicSharedMemorySize, gemm_smem);
    cudaFuncSetAttribute(egemm2_kernel, cudaFuncAttributeMaxDynamicSharedMemorySize, gemm_smem);

    // --- weight + vision conversion ---
    auto conv = [&](const float* src, size_t off, int n) {
        conv_kernel<<<(n / 4 + 255) / 256, 256>>>(src, p_wh + off, p_wl + off, n);
    };
    conv(sa_wq, OFF_SAWQ, SZ_QO); conv(sa_wk, OFF_SAWK, SZ_KV);
    conv(sa_wv, OFF_SAWV, SZ_KV); conv(sa_wo, OFF_SAWO, SZ_QO);
    conv(ca_wq, OFF_CAWQ, SZ_QO); conv(ca_wk, OFF_CAWK, SZ_KV);
    conv(ca_wv, OFF_CAWV, SZ_KV); conv(ca_wo, OFF_CAWO, SZ_QO);
    conv(ew1, OFF_EW1, EE * CC * FF);
    conv(ew2, OFF_EW2, EE * FF * CC);
    conv_kernel<<<(BB * MV * CC / 4 + 255) / 256, 256>>>(vision, p_vih, p_vil, BB * MV * CC);

    dim3 gC(CC / 128, TOK / 128);
    dim3 gKVsa(2, TOK / 128);
    dim3 gKVca(2, (BB * MV) / 128);
    dim3 gAtt(NN / 128, HH, BB);

    // --- block 1: pre-norm causal GQA self-attn + residual ---
    ln_kernel<<<TOK, 256>>>(x, ln1_g, ln1_b, p_h, p_hh, p_hl);
    gemm128<<<gC, 256, gemm_smem>>>(p_hh, p_hl, OFF_SAWQ, sa_bq, nullptr,
                                    nullptr, p_qh, p_ql, TOK, CC, CC);
    kvgemm128<<<gKVsa, 256, gemm_smem>>>(p_hh, p_hl, OFF_SAWK, sa_bk, OFF_SAWV, sa_bv,
                                         p_kh, p_kl, p_vh_, p_vl_, TOK, CC);
    flash_mma<<<gAtt, 256>>>(p_qh, p_ql, p_kh, p_kl, p_vh_, p_vl_, p_ath, p_atl, NN, 1);
    gemm128<<<gC, 256, gemm_smem>>>(p_ath, p_atl, OFF_SAWO, sa_bo, x,
                                    p_x1, nullptr, nullptr, TOK, CC, CC);

    // --- block 2: pre-norm cross-attn + residual ---
    ln_kernel<<<TOK, 256>>>(p_x1, ln2_g, ln2_b, p_h, p_hh, p_hl);
    gemm128<<<gC, 256, gemm_smem>>>(p_hh, p_hl, OFF_CAWQ, ca_bq, nullptr,
                                    nullptr, p_qh, p_ql, TOK, CC, CC);
    kvgemm128<<<gKVca, 256, gemm_smem>>>(p_vih, p_vil, OFF_CAWK, ca_bk, OFF_CAWV, ca_bv,
                                         p_kh, p_kl, p_vh_, p_vl_, BB * MV, CC);
    flash_mma<<<gAtt, 256>>>(p_qh, p_ql, p_kh, p_kl, p_vh_, p_vl_, p_ath, p_atl, MV, 0);
    gemm128<<<gC, 256, gemm_smem>>>(p_ath, p_atl, OFF_CAWO, ca_bo, p_x1,
                                    p_x2, nullptr, nullptr, TOK, CC, CC);

    // --- block 3: pre-norm MoE + residual ---
    ln_kernel<<<TOK, 256>>>(p_x2, ln3_g, ln3_b, p_h, p_hh, p_hl);
    zero_kernel<<<1, 32>>>();
    router_kernel<<<TOK / 256, 256>>>(rw, rb);
    egemm1_kernel<<<dim3(FF / 128, EROWS / 128, EE), 256, gemm_smem>>>(eb1);
    egemm2_kernel<<<dim3(CC / 128, EROWS / 128, EE), 256, gemm_smem>>>(eb2);
    combine_kernel<<<TOK, 128>>>(out);
    aux_kernel<<<1, 1>>>(out, out_size);
}

// round 9
// speedup vs baseline: 1.7785x; 1.1024x over previous
#include <cuda_runtime.h>
#include <cuda_bf16.h>
#include <mma.h>
#include <math.h>

using namespace nvcuda;

// ---------------- problem constants ----------------
#define BB 4
#define NN 2048
#define MV 576
#define CC 512
#define HH 8
#define KVH 2
#define DD 64
#define EE 8
#define TOPK 2
#define FF 2048
#define TOK (BB*NN)
#define KVDIM (KVH*DD)       // 128
#define EROWS 8192

// weight buffer offsets (elements)
#define SZ_QO (CC*CC)
#define SZ_KV (CC*KVDIM)
#define OFF_SAWQ 0
#define OFF_SAWK (OFF_SAWQ+SZ_QO)
#define OFF_SAWV (OFF_SAWK+SZ_KV)
#define OFF_SAWO (OFF_SAWV+SZ_KV)
#define OFF_CAWQ (OFF_SAWO+SZ_QO)
#define OFF_CAWK (OFF_CAWQ+SZ_QO)
#define OFF_CAWV (OFF_CAWK+SZ_KV)
#define OFF_CAWO (OFF_CAWV+SZ_KV)
#define OFF_EW1  (OFF_CAWO+SZ_QO)
#define OFF_EW2  (OFF_EW1 + (size_t)EE*CC*FF)
#define WTOT     (OFF_EW2 + (size_t)EE*FF*CC)

// ---------------- static scratch ----------------
__device__ float g_h  [(size_t)TOK*CC];     // fp32 LN out (router)
__device__ float g_x1 [(size_t)TOK*CC];
__device__ float g_x2 [(size_t)TOK*CC];
__device__ float g_eo [(size_t)EE*EROWS*CC];
__device__ __nv_bfloat16 g_h_hi [(size_t)TOK*CC];
__device__ __nv_bfloat16 g_h_lo [(size_t)TOK*CC];
__device__ __nv_bfloat16 g_q_hi [(size_t)TOK*CC];
__device__ __nv_bfloat16 g_q_lo [(size_t)TOK*CC];
__device__ __nv_bfloat16 g_k_hi [(size_t)TOK*KVDIM];
__device__ __nv_bfloat16 g_k_lo [(size_t)TOK*KVDIM];
__device__ __nv_bfloat16 g_v_hi [(size_t)TOK*KVDIM];
__device__ __nv_bfloat16 g_v_lo [(size_t)TOK*KVDIM];
__device__ __nv_bfloat16 g_att_hi[(size_t)TOK*CC];
__device__ __nv_bfloat16 g_att_lo[(size_t)TOK*CC];
__device__ __nv_bfloat16 g_vis_hi[(size_t)BB*MV*CC];
__device__ __nv_bfloat16 g_vis_lo[(size_t)BB*MV*CC];
__device__ __nv_bfloat16 g_mid_hi[(size_t)EE*EROWS*FF];
__device__ __nv_bfloat16 g_mid_lo[(size_t)EE*EROWS*FF];
__device__ __nv_bfloat16 g_w_hi[WTOT];
__device__ __nv_bfloat16 g_w_lo[WTOT];
__device__ int   g_count[EE];
__device__ float g_Psum[EE];
__device__ int   g_tokrow [TOK*TOPK];
__device__ float g_tokgate[TOK*TOPK];
__device__ int   g_tok_of_row[EE*EROWS];

// ---------------- helpers ----------------
__device__ __forceinline__ void split1(float v, __nv_bfloat16& h, __nv_bfloat16& l) {
    h = __float2bfloat16(v);
    l = __float2bfloat16(v - __bfloat162float(h));
}
__device__ __forceinline__ unsigned pk2(float lo, float hi) {
    unsigned r;
    asm("cvt.rn.bf16x2.f32 %0, %1, %2;" : "=r"(r) : "f"(hi), "f"(lo));
    return r;
}
__device__ __forceinline__ float bfrt(float x) {
    return __bfloat162float(__float2bfloat16(x));
}
__device__ __forceinline__ void mma16816(float* c, const unsigned* a, const unsigned* b) {
    asm volatile(
        "mma.sync.aligned.m16n8k16.row.col.f32.bf16.bf16.f32 "
        "{%0,%1,%2,%3},{%4,%5,%6,%7},{%8,%9},{%0,%1,%2,%3};"
        : "+f"(c[0]), "+f"(c[1]), "+f"(c[2]), "+f"(c[3])
        : "r"(a[0]), "r"(a[1]), "r"(a[2]), "r"(a[3]), "r"(b[0]), "r"(b[1]));
}
// 16B async copy; zero-fill when !valid
__device__ __forceinline__ void cp16(void* dst, const void* src, bool valid) {
    unsigned d = (unsigned)__cvta_generic_to_shared(dst);
    int sz = valid ? 16 : 0;
    asm volatile("cp.async.cg.shared.global [%0], [%1], 16, %2;\n" :: "r"(d), "l"(src), "r"(sz));
}
#define CP_COMMIT asm volatile("cp.async.commit_group;\n" ::: "memory")
#define CP_WAIT0  asm volatile("cp.async.wait_group 0;\n" ::: "memory")
#define CP_WAIT1  asm volatile("cp.async.wait_group 1;\n" ::: "memory")

// ---------------- fp32 -> hi/lo bf16 conversion ----------------
__global__ void conv_kernel(const float* __restrict__ src, __nv_bfloat16* __restrict__ hi,
                            __nv_bfloat16* __restrict__ lo, int n) {
    int i = (blockIdx.x * blockDim.x + threadIdx.x) * 4;
    if (i >= n) return;
    float4 v = *(const float4*)(src + i);
    __align__(8) __nv_bfloat16 h[4], l[4];
    split1(v.x, h[0], l[0]); split1(v.y, h[1], l[1]);
    split1(v.z, h[2], l[2]); split1(v.w, h[3], l[3]);
    *(uint2*)(hi + i) = *(uint2*)h;
    *(uint2*)(lo + i) = *(uint2*)l;
}

// ---------------- LayerNorm (fp32 + hi/lo bf16 out) ----------------
__global__ void ln_kernel(const float* __restrict__ x, const float* __restrict__ g,
                          const float* __restrict__ b, float* __restrict__ o,
                          __nv_bfloat16* __restrict__ ohi, __nv_bfloat16* __restrict__ olo) {
    int t = blockIdx.x;
    int tid = threadIdx.x;
    const float* xr = x + (size_t)t * CC;
    float v0 = xr[tid], v1 = xr[tid + 256];
    __shared__ float red[256];
    red[tid] = v0 + v1; __syncthreads();
    for (int off = 128; off > 0; off >>= 1) {
        if (tid < off) red[tid] += red[tid + off];
        __syncthreads();
    }
    float mu = red[0] * (1.0f / CC);
    __syncthreads();
    float d0 = v0 - mu, d1 = v1 - mu;
    red[tid] = d0 * d0 + d1 * d1; __syncthreads();
    for (int off = 128; off > 0; off >>= 1) {
        if (tid < off) red[tid] += red[tid + off];
        __syncthreads();
    }
    float rstd = rsqrtf(red[0] * (1.0f / CC) + 1e-6f);
    size_t base = (size_t)t * CC;
    float r0 = d0 * rstd * g[tid]       + b[tid];
    float r1 = d1 * rstd * g[tid + 256] + b[tid + 256];
    o[base + tid] = r0; o[base + tid + 256] = r1;
    __nv_bfloat16 h, l;
    split1(r0, h, l); ohi[base + tid] = h;       olo[base + tid] = l;
    split1(r1, h, l); ohi[base + tid + 256] = h; olo[base + tid + 256] = l;
}

// ---------------- wmma split-bf16 GEMM core, 2-stage cp.async pipeline ----------------
#define APAD 40
#define BPAD 136
#define CPAD 132
struct SmemGemm {
    __nv_bfloat16 Ah[2][128][APAD];
    __nv_bfloat16 Al[2][128][APAD];
    __nv_bfloat16 Bh[2][32][BPAD];
    __nv_bfloat16 Bl[2][32][BPAD];
};
#define GEMM_SMEM_BYTES 75776   // sizeof(SmemGemm)=75776 > Cs staging 128*132*4=67584

typedef wmma::fragment<wmma::accumulator, 16, 16, 16, float> AccFrag;

__device__ __forceinline__ void wmma_core(
        const __nv_bfloat16* __restrict__ Ahg, const __nv_bfloat16* __restrict__ Alg,
        const __nv_bfloat16* __restrict__ Bhg, const __nv_bfloat16* __restrict__ Blg,
        const int* __restrict__ tokidx,
        int Mr, int Nc, int Kd, int row0, int col0,
        SmemGemm* S, AccFrag (&acc)[2][4]) {
    int tid = threadIdx.x;
    int w = tid >> 5, wm = w & 3, wn = w >> 2;
    int ra = tid >> 1, kc = (tid & 1) * 16;     // A: 128 rows x 32 cols
    int rb = tid >> 3, cb = (tid & 7) * 16;     // B: 32 rows x 128 cols

    size_t arow; bool avalid;
    if (tokidx) {
        int tok = tokidx[ra];
        avalid = (tok >= 0);
        arow = (size_t)(avalid ? tok : 0) * Kd;
    } else {
        int gr = row0 + ra;
        avalid = (gr < Mr);
        arow = (size_t)(avalid ? gr : 0) * Kd;
    }

    int nch = Kd / 32;
    auto issue = [&](int c) {
        int k0 = c * 32, buf = c & 1;
        size_t ab = arow + k0 + kc;
        cp16(&S->Ah[buf][ra][kc],     Ahg + ab,     avalid);
        cp16(&S->Ah[buf][ra][kc + 8], Ahg + ab + 8, avalid);
        cp16(&S->Al[buf][ra][kc],     Alg + ab,     avalid);
        cp16(&S->Al[buf][ra][kc + 8], Alg + ab + 8, avalid);
        size_t bb = (size_t)(k0 + rb) * Nc + col0 + cb;
        cp16(&S->Bh[buf][rb][cb],     Bhg + bb,     true);
        cp16(&S->Bh[buf][rb][cb + 8], Bhg + bb + 8, true);
        cp16(&S->Bl[buf][rb][cb],     Blg + bb,     true);
        cp16(&S->Bl[buf][rb][cb + 8], Blg + bb + 8, true);
        CP_COMMIT;
    };

    issue(0);
    #pragma unroll 1
    for (int c = 0; c < nch; c++) {
        if (c + 1 < nch) { issue(c + 1); CP_WAIT1; } else { CP_WAIT0; }
        __syncthreads();
        int buf = c & 1;
        #pragma unroll
        for (int ks = 0; ks < 2; ks++) {
            wmma::fragment<wmma::matrix_a, 16,16,16, __nv_bfloat16, wmma::row_major> ah[2], al[2];
            wmma::fragment<wmma::matrix_b, 16,16,16, __nv_bfloat16, wmma::row_major> bh[4], bl[4];
            #pragma unroll
            for (int i = 0; i < 2; i++) {
                wmma::load_matrix_sync(ah[i], &S->Ah[buf][wm*32 + i*16][ks*16], APAD);
                wmma::load_matrix_sync(al[i], &S->Al[buf][wm*32 + i*16][ks*16], APAD);
            }
            #pragma unroll
            for (int j = 0; j < 4; j++) {
                wmma::load_matrix_sync(bh[j], &S->Bh[buf][ks*16][wn*64 + j*16], BPAD);
                wmma::load_matrix_sync(bl[j], &S->Bl[buf][ks*16][wn*64 + j*16], BPAD);
            }
            #pragma unroll
            for (int i = 0; i < 2; i++)
                #pragma unroll
                for (int j = 0; j < 4; j++) {
                    wmma::mma_sync(acc[i][j], ah[i], bh[j], acc[i][j]);
                    wmma::mma_sync(acc[i][j], ah[i], bl[j], acc[i][j]);
                    wmma::mma_sync(acc[i][j], al[i], bh[j], acc[i][j]);
                }
        }
        __syncthreads();   // readers done before buf is overwritten two chunks later
    }
}

__device__ __forceinline__ void stage_acc(AccFrag (&acc)[2][4], float (*Cs)[CPAD], int tid) {
    int w = tid >> 5, wm = w & 3, wn = w >> 2;
    #pragma unroll
    for (int i = 0; i < 2; i++)
        #pragma unroll
        for (int j = 0; j < 4; j++)
            wmma::store_matrix_sync(&Cs[wm*32 + i*16][wn*64 + j*16], acc[i][j],
                                    CPAD, wmma::mem_row_major);
    __syncthreads();
}

// ---------------- generic GEMM: fp32 out (bias/resid) OR hi/lo bf16 out ----------------
__global__ void __launch_bounds__(256) gemm128(
        const __nv_bfloat16* __restrict__ Ahg, const __nv_bfloat16* __restrict__ Alg,
        int woff, const float* __restrict__ bias, const float* __restrict__ resid,
        float* __restrict__ out,
        __nv_bfloat16* __restrict__ ohi, __nv_bfloat16* __restrict__ olo,
        int Mr, int Nc, int Kd) {
    extern __shared__ char smraw[];
    SmemGemm* S = (SmemGemm*)smraw;
    float (*Cs)[CPAD] = (float(*)[CPAD])smraw;
    int tid = threadIdx.x;
    int row0 = blockIdx.y * 128, col0 = blockIdx.x * 128;
    AccFrag acc[2][4];
    #pragma unroll
    for (int i = 0; i < 2; i++)
        #pragma unroll
        for (int j = 0; j < 4; j++) wmma::fill_fragment(acc[i][j], 0.0f);
    wmma_core(Ahg, Alg, g_w_hi + woff, g_w_lo + woff, nullptr, Mr, Nc, Kd, row0, col0, S, acc);
    stage_acc(acc, Cs, tid);
    #pragma unroll
    for (int u = 0; u < 16; u++) {
        int f = tid + u * 256;
        int r = f >> 5, c = (f & 31) * 4;
        int gr = row0 + r;
        if (gr >= Mr) continue;
        int gc = col0 + c;
        float4 v = *(float4*)&Cs[r][c];
        if (bias) { v.x += bias[gc]; v.y += bias[gc+1]; v.z += bias[gc+2]; v.w += bias[gc+3]; }
        if (resid) {
            float4 rr = *(const float4*)(resid + (size_t)gr * Nc + gc);
            v.x += rr.x; v.y += rr.y; v.z += rr.z; v.w += rr.w;
        }
        if (out) {
            *(float4*)(out + (size_t)gr * Nc + gc) = v;
        } else {
            __align__(8) __nv_bfloat16 hh[4], ll[4];
            split1(v.x, hh[0], ll[0]); split1(v.y, hh[1], ll[1]);
            split1(v.z, hh[2], ll[2]); split1(v.w, hh[3], ll[3]);
            *(uint2*)(ohi + (size_t)gr * Nc + gc) = *(uint2*)hh;
            *(uint2*)(olo + (size_t)gr * Nc + gc) = *(uint2*)ll;
        }
    }
}

// ---------------- fused K+V projection -> hi/lo bf16 ----------------
__global__ void __launch_bounds__(256) kvgemm128(
        const __nv_bfloat16* __restrict__ Ahg, const __nv_bfloat16* __restrict__ Alg,
        int woffk, const float* __restrict__ bk,
        int woffv, const float* __restrict__ bv,
        __nv_bfloat16* __restrict__ okh, __nv_bfloat16* __restrict__ okl,
        __nv_bfloat16* __restrict__ ovh, __nv_bfloat16* __restrict__ ovl,
        int Mr, int Kd) {
    extern __shared__ char smraw[];
    SmemGemm* S = (SmemGemm*)smraw;
    float (*Cs)[CPAD] = (float(*)[CPAD])smraw;
    int woff          = (blockIdx.x == 0) ? woffk : woffv;
    const float* bias = (blockIdx.x == 0) ? bk : bv;
    __nv_bfloat16* oh = (blockIdx.x == 0) ? okh : ovh;
    __nv_bfloat16* ol = (blockIdx.x == 0) ? okl : ovl;
    int tid = threadIdx.x;
    int row0 = blockIdx.y * 128;
    AccFrag acc[2][4];
    #pragma unroll
    for (int i = 0; i < 2; i++)
        #pragma unroll
        for (int j = 0; j < 4; j++) wmma::fill_fragment(acc[i][j], 0.0f);
    wmma_core(Ahg, Alg, g_w_hi + woff, g_w_lo + woff, nullptr, Mr, KVDIM, Kd, row0, 0, S, acc);
    stage_acc(acc, Cs, tid);
    #pragma unroll
    for (int u = 0; u < 16; u++) {
        int f = tid + u * 256;
        int r = f >> 5, c = (f & 31) * 4;
        int gr = row0 + r;
        if (gr >= Mr) continue;
        float4 v = *(float4*)&Cs[r][c];
        v.x += bias[c]; v.y += bias[c+1]; v.z += bias[c+2]; v.w += bias[c+3];
        __align__(8) __nv_bfloat16 hh[4], ll[4];
        split1(v.x, hh[0], ll[0]); split1(v.y, hh[1], ll[1]);
        split1(v.z, hh[2], ll[2]); split1(v.w, hh[3], ll[3]);
        *(uint2*)(oh + (size_t)gr * KVDIM + c) = *(uint2*)hh;
        *(uint2*)(ol + (size_t)gr * KVDIM + c) = *(uint2*)ll;
    }
}

// ---------------- FA2 flash attention: mma.m16n8k16 split-bf16 ----------------
#define KPAD 72
__global__ void __launch_bounds__(256) flash_mma(
        const __nv_bfloat16* __restrict__ qhi, const __nv_bfloat16* __restrict__ qlo,
        const __nv_bfloat16* __restrict__ khi, const __nv_bfloat16* __restrict__ klo,
        const __nv_bfloat16* __restrict__ vhi, const __nv_bfloat16* __restrict__ vlo,
        __nv_bfloat16* __restrict__ ohi, __nv_bfloat16* __restrict__ olo,
        int n_kv, int causal) {
    __shared__ __nv_bfloat16 Kh[64][KPAD], Kl[64][KPAD], Vth[64][KPAD], Vtl[64][KPAD];
    int qt = blockIdx.x, h = blockIdx.y, b = blockIdx.z;
    int g = h >> 2;
    int tid = threadIdx.x, w = tid >> 5, lane = tid & 31;
    int r0 = lane >> 2, tq = lane & 3;
    int qrow = qt * 128 + w * 16 + r0;

    unsigned qah[4][4], qal[4][4];
    {
        const __nv_bfloat16* q0h = qhi + ((size_t)(b * NN + qrow)) * CC + h * DD;
        const __nv_bfloat16* q1h = qhi + ((size_t)(b * NN + qrow + 8)) * CC + h * DD;
        const __nv_bfloat16* q0l = qlo + ((size_t)(b * NN + qrow)) * CC + h * DD;
        const __nv_bfloat16* q1l = qlo + ((size_t)(b * NN + qrow + 8)) * CC + h * DD;
        #pragma unroll
        for (int ks = 0; ks < 4; ks++) {
            int c = ks * 16 + tq * 2;
            qah[ks][0] = *(const unsigned*)(q0h + c);
            qah[ks][1] = *(const unsigned*)(q1h + c);
            qah[ks][2] = *(const unsigned*)(q0h + c + 8);
            qah[ks][3] = *(const unsigned*)(q1h + c + 8);
            qal[ks][0] = *(const unsigned*)(q0l + c);
            qal[ks][1] = *(const unsigned*)(q1l + c);
            qal[ks][2] = *(const unsigned*)(q0l + c + 8);
            qal[ks][3] = *(const unsigned*)(q1l + c + 8);
        }
    }

    float m0 = -1e30f, m1 = -1e30f, l0 = 0.0f, l1 = 0.0f;
    float o[8][4] = {};

    int key_l = tid >> 2, dseg = (tid & 3) * 16;
    int nkt = causal ? (2 * qt + 2) : (n_kv / 64);
    for (int kt = 0; kt < nkt; kt++) {
        __syncthreads();
        {
            size_t base = ((size_t)(b * n_kv + kt * 64 + key_l)) * KVDIM + g * DD + dseg;
            *(uint4*)&Kh[key_l][dseg]     = *(const uint4*)(khi + base);
            *(uint4*)&Kh[key_l][dseg + 8] = *(const uint4*)(khi + base + 8);
            *(uint4*)&Kl[key_l][dseg]     = *(const uint4*)(klo + base);
            *(uint4*)&Kl[key_l][dseg + 8] = *(const uint4*)(klo + base + 8);
            const __nv_bfloat16* vh = vhi + base;
            const __nv_bfloat16* vl = vlo + base;
            #pragma unroll
            for (int i = 0; i < 16; i++) {
                Vth[dseg + i][key_l] = vh[i];
                Vtl[dseg + i][key_l] = vl[i];
            }
        }
        __syncthreads();

        float sc[8][4] = {};
        #pragma unroll
        for (int nt = 0; nt < 8; nt++) {
            int krow = nt * 8 + r0;
            #pragma unroll
            for (int ks = 0; ks < 4; ks++) {
                int c = ks * 16 + tq * 2;
                unsigned bh[2], bl[2];
                bh[0] = *(const unsigned*)&Kh[krow][c];
                bh[1] = *(const unsigned*)&Kh[krow][c + 8];
                bl[0] = *(const unsigned*)&Kl[krow][c];
                bl[1] = *(const unsigned*)&Kl[krow][c + 8];
                mma16816(sc[nt], qah[ks], bh);
                mma16816(sc[nt], qah[ks], bl);
                mma16816(sc[nt], qal[ks], bh);
            }
        }
        bool maskit = causal && (kt >= 2 * qt);
        #pragma unroll
        for (int nt = 0; nt < 8; nt++) {
            #pragma unroll
            for (int j = 0; j < 4; j++) {
                float v = sc[nt][j] * 0.125f;
                if (maskit) {
                    int col = kt * 64 + nt * 8 + tq * 2 + (j & 1);
                    int row = qt * 128 + w * 16 + r0 + ((j >> 1) ? 8 : 0);
                    if (col > row) v = -1e9f;
                }
                sc[nt][j] = v;
            }
        }
        float rm0 = -1e30f, rm1 = -1e30f;
        #pragma unroll
        for (int nt = 0; nt < 8; nt++) {
            rm0 = fmaxf(rm0, fmaxf(sc[nt][0], sc[nt][1]));
            rm1 = fmaxf(rm1, fmaxf(sc[nt][2], sc[nt][3]));
        }
        #pragma unroll
        for (int off = 1; off < 4; off <<= 1) {
            rm0 = fmaxf(rm0, __shfl_xor_sync(0xffffffffu, rm0, off));
            rm1 = fmaxf(rm1, __shfl_xor_sync(0xffffffffu, rm1, off));
        }
        float mn0 = fmaxf(m0, rm0), mn1 = fmaxf(m1, rm1);
        float al0 = __expf(m0 - mn0), al1 = __expf(m1 - mn1);
        m0 = mn0; m1 = mn1;
        float rs0 = 0.0f, rs1 = 0.0f;
        #pragma unroll
        for (int nt = 0; nt < 8; nt++) {
            sc[nt][0] = __expf(sc[nt][0] - mn0);
            sc[nt][1] = __expf(sc[nt][1] - mn0);
            sc[nt][2] = __expf(sc[nt][2] - mn1);
            sc[nt][3] = __expf(sc[nt][3] - mn1);
            rs0 += sc[nt][0] + sc[nt][1];
            rs1 += sc[nt][2] + sc[nt][3];
        }
        #pragma unroll
        for (int off = 1; off < 4; off <<= 1) {
            rs0 += __shfl_xor_sync(0xffffffffu, rs0, off);
            rs1 += __shfl_xor_sync(0xffffffffu, rs1, off);
        }
        l0 = l0 * al0 + rs0;
        l1 = l1 * al1 + rs1;
        #pragma unroll
        for (int nt = 0; nt < 8; nt++) {
            o[nt][0] *= al0; o[nt][1] *= al0;
            o[nt][2] *= al1; o[nt][3] *= al1;
        }
        #pragma unroll
        for (int kp = 0; kp < 4; kp++) {
            unsigned pah[4], pal[4];
            {
                float x0 = sc[2*kp][0],   x1 = sc[2*kp][1];
                float x2 = sc[2*kp][2],   x3 = sc[2*kp][3];
                float y0 = sc[2*kp+1][0], y1 = sc[2*kp+1][1];
                float y2 = sc[2*kp+1][2], y3 = sc[2*kp+1][3];
                pah[0] = pk2(x0, x1); pah[1] = pk2(x2, x3);
                pah[2] = pk2(y0, y1); pah[3] = pk2(y2, y3);
                pal[0] = pk2(x0 - bfrt(x0), x1 - bfrt(x1));
                pal[1] = pk2(x2 - bfrt(x2), x3 - bfrt(x3));
                pal[2] = pk2(y0 - bfrt(y0), y1 - bfrt(y1));
                pal[3] = pk2(y2 - bfrt(y2), y3 - bfrt(y3));
            }
            #pragma unroll
            for (int nt = 0; nt < 8; nt++) {
                int drow = nt * 8 + r0;
                int c = kp * 16 + tq * 2;
                unsigned bh[2], bl[2];
                bh[0] = *(const unsigned*)&Vth[drow][c];
                bh[1] = *(const unsigned*)&Vth[drow][c + 8];
                bl[0] = *(const unsigned*)&Vtl[drow][c];
                bl[1] = *(const unsigned*)&Vtl[drow][c + 8];
                mma16816(o[nt], pah, bh);
                mma16816(o[nt], pah, bl);
                mma16816(o[nt], pal, bh);
            }
        }
    }
    float inv0 = 1.0f / l0, inv1 = 1.0f / l1;
    size_t base0 = ((size_t)(b * NN + qrow)) * CC + h * DD;
    size_t base1 = ((size_t)(b * NN + qrow + 8)) * CC + h * DD;
    #pragma unroll
    for (int nt = 0; nt < 8; nt++) {
        int d = nt * 8 + tq * 2;
        float v0 = o[nt][0] * inv0, v1 = o[nt][1] * inv0;
        float v2 = o[nt][2] * inv1, v3 = o[nt][3] * inv1;
        *(unsigned*)(ohi + base0 + d) = pk2(bfrt(v0), bfrt(v1));
        *(unsigned*)(olo + base0 + d) = pk2(v0 - bfrt(v0), v1 - bfrt(v1));
        *(unsigned*)(ohi + base1 + d) = pk2(bfrt(v2), bfrt(v3));
        *(unsigned*)(olo + base1 + d) = pk2(v2 - bfrt(v2), v3 - bfrt(v3));
    }
}

// ---------------- MoE routing ----------------
__global__ void zero_kernel() {
    int t = threadIdx.x;
    if (t < EE) { g_count[t] = 0; g_Psum[t] = 0.0f; }
}

__global__ void router_kernel(const float* __restrict__ rw, const float* __restrict__ rb) {
    __shared__ float sP[EE];
    int tid = threadIdx.x;
    if (tid < EE) sP[tid] = 0.0f;
    __syncthreads();
    int t = blockIdx.x * blockDim.x + tid;
    float logit[EE];
    const float* hrow = g_h + (size_t)t * CC;
    #pragma unroll
    for (int e = 0; e < EE; e++) logit[e] = rb[e];
    for (int k = 0; k < CC; k++) {
        float hv = hrow[k];
        const float* wr = rw + k * EE;
        #pragma unroll
        for (int e = 0; e < EE; e++) logit[e] += hv * wr[e];
    }
    float mx = logit[0];
    #pragma unroll
    for (int e = 1; e < EE; e++) mx = fmaxf(mx, logit[e]);
    float p[EE], ps = 0.0f;
    #pragma unroll
    for (int e = 0; e < EE; e++) { p[e] = __expf(logit[e] - mx); ps += p[e]; }
    float invs = 1.0f / ps;
    #pragma unroll
    for (int e = 0; e < EE; e++) p[e] *= invs;
    int i0 = 0;
    #pragma unroll
    for (int e = 1; e < EE; e++) if (p[e] > p[i0]) i0 = e;
    int i1 = (i0 == 0) ? 1 : 0;
    #pragma unroll
    for (int e = 0; e < EE; e++) if (e != i0 && p[e] > p[i1]) i1 = e;
    float gs = p[i0] + p[i1];
    float g0 = p[i0] / gs, g1 = p[i1] / gs;
    int s0 = atomicAdd(&g_count[i0], 1);
    int s1 = atomicAdd(&g_count[i1], 1);
    int r0 = i0 * EROWS + s0, r1 = i1 * EROWS + s1;
    g_tok_of_row[r0] = t; g_tok_of_row[r1] = t;
    g_tokrow[t * 2] = r0; g_tokrow[t * 2 + 1] = r1;
    g_tokgate[t * 2] = g0; g_tokgate[t * 2 + 1] = g1;
    #pragma unroll
    for (int e = 0; e < EE; e++) atomicAdd(&sP[e], p[e]);
    __syncthreads();
    if (tid < EE) atomicAdd(&g_Psum[tid], sP[tid]);
}

// ---------------- expert GEMM 1 (gathered A, GELU -> mid hi/lo) ----------------
__global__ void __launch_bounds__(256) egemm1_kernel(const float* __restrict__ eb1) {
    int e = blockIdx.z;
    int cnt = g_count[e];
    int row0 = blockIdx.y * 128;
    if (row0 >= cnt) return;
    int col0 = blockIdx.x * 128;
    extern __shared__ char smraw[];
    SmemGemm* S = (SmemGemm*)smraw;
    float (*Cs)[CPAD] = (float(*)[CPAD])smraw;
    __shared__ int s_tok[128];
    int tid = threadIdx.x;
    if (tid < 128) {
        int gr = row0 + tid;
        s_tok[tid] = (gr < cnt) ? g_tok_of_row[e * EROWS + gr] : -1;
    }
    __syncthreads();
    AccFrag acc[2][4];
    #pragma unroll
    for (int i = 0; i < 2; i++)
        #pragma unroll
        for (int j = 0; j < 4; j++) wmma::fill_fragment(acc[i][j], 0.0f);
    size_t woff = OFF_EW1 + (size_t)e * CC * FF;
    wmma_core(g_h_hi, g_h_lo, g_w_hi + woff, g_w_lo + woff, s_tok, 0, FF, CC, 0, col0, S, acc);
    stage_acc(acc, Cs, tid);
    #pragma unroll
    for (int u = 0; u < 16; u++) {
        int f = tid + u * 256;
        int r = f >> 5, c = (f & 31) * 4;
        if (row0 + r >= cnt) continue;
        int gc = col0 + c;
        float4 v = *(float4*)&Cs[r][c];
        float vv[4] = {v.x, v.y, v.z, v.w};
        __align__(8) __nv_bfloat16 hh[4], ll[4];
        #pragma unroll
        for (int j = 0; j < 4; j++) {
            float xx = vv[j] + eb1[e * FF + gc + j];
            float uu = 0.7978845608028654f * (xx + 0.044715f * xx * xx * xx);
            float ge = 0.5f * xx * (1.0f + tanhf(uu));
            split1(ge, hh[j], ll[j]);
        }
        size_t idx = ((size_t)e * EROWS + row0 + r) * FF + gc;
        *(uint2*)(g_mid_hi + idx) = *(uint2*)hh;
        *(uint2*)(g_mid_lo + idx) = *(uint2*)ll;
    }
}

// ---------------- expert GEMM 2 ----------------
__global__ void __launch_bounds__(256) egemm2_kernel(const float* __restrict__ eb2) {
    int e = blockIdx.z;
    int cnt = g_count[e];
    int row0 = blockIdx.y * 128;
    if (row0 >= cnt) return;
    int col0 = blockIdx.x * 128;
    extern __shared__ char smraw[];
    SmemGemm* S = (SmemGemm*)smraw;
    float (*Cs)[CPAD] = (float(*)[CPAD])smraw;
    int tid = threadIdx.x;
    AccFrag acc[2][4];
    #pragma unroll
    for (int i = 0; i < 2; i++)
        #pragma unroll
        for (int j = 0; j < 4; j++) wmma::fill_fragment(acc[i][j], 0.0f);
    size_t woff = OFF_EW2 + (size_t)e * FF * CC;
    wmma_core(g_mid_hi + (size_t)e * EROWS * FF, g_mid_lo + (size_t)e * EROWS * FF,
              g_w_hi + woff, g_w_lo + woff, nullptr, cnt, CC, FF, row0, col0, S, acc);
    stage_acc(acc, Cs, tid);
    #pragma unroll
    for (int u = 0; u < 16; u++) {
        int f = tid + u * 256;
        int r = f >> 5, c = (f & 31) * 4;
        if (row0 + r >= cnt) continue;
        int gc = col0 + c;
        float4 v = *(float4*)&Cs[r][c];
        v.x += eb2[e * CC + gc];     v.y += eb2[e * CC + gc + 1];
        v.z += eb2[e * CC + gc + 2]; v.w += eb2[e * CC + gc + 3];
        *(float4*)&g_eo[((size_t)e * EROWS + row0 + r) * CC + gc] = v;
    }
}

// ---------------- combine + aux ----------------
__global__ void combine_kernel(float* __restrict__ out) {
    int t = blockIdx.x;
    int tid = threadIdx.x;
    int r0 = g_tokrow[t * 2], r1 = g_tokrow[t * 2 + 1];
    float g0 = g_tokgate[t * 2], g1 = g_tokgate[t * 2 + 1];
    const float* x2 = g_x2 + (size_t)t * CC;
    const float* e0 = g_eo + (size_t)r0 * CC;
    const float* e1 = g_eo + (size_t)r1 * CC;
    float* orow = out + (size_t)t * CC;
    for (int c = tid; c < CC; c += 128)
        orow[c] = x2[c] + g0 * e0[c] + g1 * e1[c];
}

__global__ void aux_kernel(float* __restrict__ out, int out_size) {
    if (threadIdx.x == 0 && blockIdx.x == 0) {
        float a = 0.0f;
        for (int e = 0; e < EE; e++)
            a += (g_count[e] / (float)TOK) * (g_Psum[e] / (float)TOK);
        a *= (float)EE;
        if (out_size > TOK * CC) out[TOK * CC] = a;
    }
}

// ---------------- launch ----------------
extern "C" void kernel_launch(void* const* d_in, const int* in_sizes, int n_in,
                              void* d_out, int out_size) {
    const float* x      = (const float*)d_in[0];
    const float* vision = (const float*)d_in[1];
    const float* ln1_g = (const float*)d_in[2];  const float* ln1_b = (const float*)d_in[3];
    const float* ln2_g = (const float*)d_in[4];  const float* ln2_b = (const float*)d_in[5];
    const float* ln3_g = (const float*)d_in[6];  const float* ln3_b = (const float*)d_in[7];
    const float* sa_wq = (const float*)d_in[8];  const float* sa_bq = (const float*)d_in[9];
    const float* sa_wk = (const float*)d_in[10]; const float* sa_bk = (const float*)d_in[11];
    const float* sa_wv = (const float*)d_in[12]; const float* sa_bv = (const float*)d_in[13];
    const float* sa_wo = (const float*)d_in[14]; const float* sa_bo = (const float*)d_in[15];
    const float* ca_wq = (const float*)d_in[16]; const float* ca_bq = (const float*)d_in[17];
    const float* ca_wk = (const float*)d_in[18]; const float* ca_bk = (const float*)d_in[19];
    const float* ca_wv = (const float*)d_in[20]; const float* ca_bv = (const float*)d_in[21];
    const float* ca_wo = (const float*)d_in[22]; const float* ca_bo = (const float*)d_in[23];
    const float* rw    = (const float*)d_in[24]; const float* rb    = (const float*)d_in[25];
    const float* ew1   = (const float*)d_in[26]; const float* eb1   = (const float*)d_in[27];
    const float* ew2   = (const float*)d_in[28]; const float* eb2   = (const float*)d_in[29];
    float* out = (float*)d_out;

    float *p_h, *p_x1, *p_x2;
    __nv_bfloat16 *p_hh, *p_hl, *p_qh, *p_ql, *p_kh, *p_kl, *p_vh_, *p_vl_;
    __nv_bfloat16 *p_ath, *p_atl, *p_vih, *p_vil, *p_wh, *p_wl;
    cudaGetSymbolAddress((void**)&p_h,  g_h);
    cudaGetSymbolAddress((void**)&p_x1, g_x1);
    cudaGetSymbolAddress((void**)&p_x2, g_x2);
    cudaGetSymbolAddress((void**)&p_hh, g_h_hi);
    cudaGetSymbolAddress((void**)&p_hl, g_h_lo);
    cudaGetSymbolAddress((void**)&p_qh, g_q_hi);
    cudaGetSymbolAddress((void**)&p_ql, g_q_lo);
    cudaGetSymbolAddress((void**)&p_kh, g_k_hi);
    cudaGetSymbolAddress((void**)&p_kl, g_k_lo);
    cudaGetSymbolAddress((void**)&p_vh_, g_v_hi);
    cudaGetSymbolAddress((void**)&p_vl_, g_v_lo);
    cudaGetSymbolAddress((void**)&p_ath, g_att_hi);
    cudaGetSymbolAddress((void**)&p_atl, g_att_lo);
    cudaGetSymbolAddress((void**)&p_vih, g_vis_hi);
    cudaGetSymbolAddress((void**)&p_vil, g_vis_lo);
    cudaGetSymbolAddress((void**)&p_wh, g_w_hi);
    cudaGetSymbolAddress((void**)&p_wl, g_w_lo);

    const int gemm_smem = GEMM_SMEM_BYTES;
    cudaFuncSetAttribute(gemm128,       cudaFuncAttributeMaxDynamicSharedMemorySize, gemm_smem);
    cudaFuncSetAttribute(kvgemm128,     cudaFuncAttributeMaxDynamicSharedMemorySize, gemm_smem);
    cudaFuncSetAttribute(egemm1_kernel, cudaFuncAttributeMaxDynamicSharedMemorySize, gemm_smem);
    cudaFuncSetAttribute(egemm2_kernel, cudaFuncAttributeMaxDynamicSharedMemorySize, gemm_smem);

    // --- weight + vision conversion ---
    auto conv = [&](const float* src, size_t off, int n) {
        conv_kernel<<<(n / 4 + 255) / 256, 256>>>(src, p_wh + off, p_wl + off, n);
    };
    conv(sa_wq, OFF_SAWQ, SZ_QO); conv(sa_wk, OFF_SAWK, SZ_KV);
    conv(sa_wv, OFF_SAWV, SZ_KV); conv(sa_wo, OFF_SAWO, SZ_QO);
    conv(ca_wq, OFF_CAWQ, SZ_QO); conv(ca_wk, OFF_CAWK, SZ_KV);
    conv(ca_wv, OFF_CAWV, SZ_KV); conv(ca_wo, OFF_CAWO, SZ_QO);
    conv(ew1, OFF_EW1, EE * CC * FF);
    conv(ew2, OFF_EW2, EE * FF * CC);
    conv_kernel<<<(BB * MV * CC / 4 + 255) / 256, 256>>>(vision, p_vih, p_vil, BB * MV * CC);

    dim3 gC(CC / 128, TOK / 128);
    dim3 gKVsa(2, TOK / 128);
    dim3 gKVca(2, (BB * MV) / 128);
    dim3 gAtt(NN / 128, HH, BB);

    // --- block 1: pre-norm causal GQA self-attn + residual ---
    ln_kernel<<<TOK, 256>>>(x, ln1_g, ln1_b, p_h, p_hh, p_hl);
    gemm128<<<gC, 256, gemm_smem>>>(p_hh, p_hl, OFF_SAWQ, sa_bq, nullptr,
                                    nullptr, p_qh, p_ql, TOK, CC, CC);
    kvgemm128<<<gKVsa, 256, gemm_smem>>>(p_hh, p_hl, OFF_SAWK, sa_bk, OFF_SAWV, sa_bv,
                                         p_kh, p_kl, p_vh_, p_vl_, TOK, CC);
    flash_mma<<<gAtt, 256>>>(p_qh, p_ql, p_kh, p_kl, p_vh_, p_vl_, p_ath, p_atl, NN, 1);
    gemm128<<<gC, 256, gemm_smem>>>(p_ath, p_atl, OFF_SAWO, sa_bo, x,
                                    p_x1, nullptr, nullptr, TOK, CC, CC);

    // --- block 2: pre-norm cross-attn + residual ---
    ln_kernel<<<TOK, 256>>>(p_x1, ln2_g, ln2_b, p_h, p_hh, p_hl);
    gemm128<<<gC, 256, gemm_smem>>>(p_hh, p_hl, OFF_CAWQ, ca_bq, nullptr,
                                    nullptr, p_qh, p_ql, TOK, CC, CC);
    kvgemm128<<<gKVca, 256, gemm_smem>>>(p_vih, p_vil, OFF_CAWK, ca_bk, OFF_CAWV, ca_bv,
                                         p_kh, p_kl, p_vh_, p_vl_, BB * MV, CC);
    flash_mma<<<gAtt, 256>>>(p_qh, p_ql, p_kh, p_kl, p_vh_, p_vl_, p_ath, p_atl, MV, 0);
    gemm128<<<gC, 256, gemm_smem>>>(p_ath, p_atl, OFF_CAWO, ca_bo, p_x1,
                                    p_x2, nullptr, nullptr, TOK, CC, CC);

    // --- block 3: pre-norm MoE + residual ---
    ln_kernel<<<TOK, 256>>>(p_x2, ln3_g, ln3_b, p_h, p_hh, p_hl);
    zero_kernel<<<1, 32>>>();
    router_kernel<<<TOK / 256, 256>>>(rw, rb);
    egemm1_kernel<<<dim3(FF / 128, EROWS / 128, EE), 256, gemm_smem>>>(eb1);
    egemm2_kernel<<<dim3(CC / 128, EROWS / 128, EE), 256, gemm_smem>>>(eb2);
    combine_kernel<<<TOK, 128>>>(out);
    aux_kernel<<<1, 1>>>(out, out_size);
}